// round 1
// baseline (speedup 1.0000x reference)
#include <cuda_runtime.h>
#include <math.h>
#include <stdint.h>

// ---------------- problem constants ----------------
#define TT    2048        // B*L tokens
#define BB    2
#define LL    1024
#define DD    512
#define NSt   16
#define RR    32
#define PW    1088        // 2D + R + 2N
#define DFF   2048
#define VOC   50000
#define DEPTH 6

// ---------------- device scratch (no allocs allowed) ----------------
__device__ float g_x   [TT * DD];
__device__ float g_ln  [TT * DD];
__device__ float g_proj[TT * PW];
__device__ float g_u   [TT * DD];
__device__ float g_dt  [TT * DD];
__device__ float g_y   [TT * DD];
__device__ float g_ff  [TT * DFF];
__device__ float g_te  [BB * DD];

// ---------------- time-embedding MLP (tiny) ----------------
__global__ void te_kernel(const int* __restrict__ t_in,
                          const float* __restrict__ w1, const float* __restrict__ b1,
                          const float* __restrict__ w2, const float* __restrict__ b2,
                          float* __restrict__ te)
{
    int b = blockIdx.x;
    int tid = threadIdx.x;            // 256 threads
    __shared__ float s0[DD];          // sinusoidal embedding
    __shared__ float h1[4 * DD];      // hidden 2048

    double tv = (double)t_in[b];
    // half = 256; f = exp(i * (-log(10000)/255))
    {
        double f = exp((double)tid * (-9.210340371976184 / 255.0));
        double e = tv * f;
        s0[tid]       = (float)sin(e);
        s0[tid + 256] = (float)cos(e);
    }
    __syncthreads();

    for (int j = tid; j < 4 * DD; j += 256) {
        const float* wr = w1 + (size_t)j * DD;
        float acc = b1[j];
        #pragma unroll 8
        for (int k = 0; k < DD; k++) acc = fmaf(s0[k], wr[k], acc);
        h1[j] = acc / (1.0f + expf(-acc));   // silu
    }
    __syncthreads();

    for (int j = tid; j < DD; j += 256) {
        const float* wr = w2 + (size_t)j * (4 * DD);
        float acc = b2[j];
        #pragma unroll 8
        for (int k = 0; k < 4 * DD; k++) acc = fmaf(h1[k], wr[k], acc);
        te[b * DD + j] = acc;
    }
}

// ---------------- embedding gather + te add ----------------
__global__ void embed_kernel(const int* __restrict__ x_t,
                             const float* __restrict__ tok_emb,
                             const float* __restrict__ te,
                             float* __restrict__ x)
{
    int idx = blockIdx.x * 256 + threadIdx.x;   // over TT*DD
    int d = idx & (DD - 1);
    int t = idx >> 9;
    int b = t >> 10;
    int tok = x_t[t];
    x[idx] = tok_emb[(size_t)tok * DD + d] + te[b * DD + d];
}

// ---------------- LayerNorm (two-pass, per token) ----------------
__global__ __launch_bounds__(256) void ln_kernel(const float* __restrict__ x,
                                                 const float* __restrict__ g,
                                                 const float* __restrict__ bta,
                                                 float* __restrict__ o)
{
    int t = blockIdx.x;
    int tid = threadIdx.x;
    const float* row = x + (size_t)t * DD;
    float v0 = row[tid], v1 = row[tid + 256];

    __shared__ float red[8];
    __shared__ float mean_s, rstd_s;

    float s = v0 + v1;
    #pragma unroll
    for (int off = 16; off > 0; off >>= 1) s += __shfl_xor_sync(0xffffffffu, s, off);
    if ((tid & 31) == 0) red[tid >> 5] = s;
    __syncthreads();
    if (tid == 0) {
        float tot = 0.f;
        #pragma unroll
        for (int i = 0; i < 8; i++) tot += red[i];
        mean_s = tot * (1.0f / DD);
    }
    __syncthreads();
    float mu = mean_s;
    float d0 = v0 - mu, d1 = v1 - mu;
    float q = d0 * d0 + d1 * d1;
    #pragma unroll
    for (int off = 16; off > 0; off >>= 1) q += __shfl_xor_sync(0xffffffffu, q, off);
    if ((tid & 31) == 0) red[tid >> 5] = q;
    __syncthreads();
    if (tid == 0) {
        float tot = 0.f;
        #pragma unroll
        for (int i = 0; i < 8; i++) tot += red[i];
        rstd_s = rsqrtf(tot * (1.0f / DD) + 1e-5f);
    }
    __syncthreads();
    float rs = rstd_s;
    o[(size_t)t * DD + tid]       = d0 * rs * g[tid]       + bta[tid];
    o[(size_t)t * DD + tid + 256] = d1 * rs * g[tid + 256] + bta[tid + 256];
}

// ---------------- generic fp32 GEMM: C[M,N] = A[M,K] @ W[N,K]^T ----------------
// EPI: 0 = none, 1 = softplus, 2 = exact gelu.  ACC: C += result.
template <int EPI, bool ACC>
__global__ __launch_bounds__(256) void gemm_kernel(
    const float* __restrict__ A, int lda,
    const float* __restrict__ W, int ldw,
    const float* __restrict__ bias,
    float* __restrict__ C, int ldc,
    int M, int N, int K)
{
    __shared__ float As[8][128];
    __shared__ float Ws[8][128];

    const int tid  = threadIdx.x;
    const int brow = blockIdx.y * 128;
    const int bcol = blockIdx.x * 128;
    const int lr = tid >> 1;          // 0..127 (tile row for loads)
    const int lk = (tid & 1) * 4;     // 0 or 4 (k offset for float4 load)
    const int ty = tid >> 4;          // 0..15
    const int tx = tid & 15;          // 0..15

    float acc[8][8];
    #pragma unroll
    for (int i = 0; i < 8; i++)
        #pragma unroll
        for (int j = 0; j < 8; j++) acc[i][j] = 0.f;

    for (int k0 = 0; k0 < K; k0 += 8) {
        float4 av = make_float4(0.f, 0.f, 0.f, 0.f);
        float4 wv = make_float4(0.f, 0.f, 0.f, 0.f);
        if (brow + lr < M) av = *(const float4*)(A + (size_t)(brow + lr) * lda + k0 + lk);
        if (bcol + lr < N) wv = *(const float4*)(W + (size_t)(bcol + lr) * ldw + k0 + lk);
        As[lk + 0][lr] = av.x; As[lk + 1][lr] = av.y; As[lk + 2][lr] = av.z; As[lk + 3][lr] = av.w;
        Ws[lk + 0][lr] = wv.x; Ws[lk + 1][lr] = wv.y; Ws[lk + 2][lr] = wv.z; Ws[lk + 3][lr] = wv.w;
        __syncthreads();

        #pragma unroll
        for (int kk = 0; kk < 8; kk++) {
            float4 a0 = *(const float4*)&As[kk][ty * 8];
            float4 a1 = *(const float4*)&As[kk][ty * 8 + 4];
            float4 b0 = *(const float4*)&Ws[kk][tx * 8];
            float4 b1 = *(const float4*)&Ws[kk][tx * 8 + 4];
            float ar[8] = {a0.x, a0.y, a0.z, a0.w, a1.x, a1.y, a1.z, a1.w};
            float br[8] = {b0.x, b0.y, b0.z, b0.w, b1.x, b1.y, b1.z, b1.w};
            #pragma unroll
            for (int i = 0; i < 8; i++)
                #pragma unroll
                for (int j = 0; j < 8; j++)
                    acc[i][j] = fmaf(ar[i], br[j], acc[i][j]);
        }
        __syncthreads();
    }

    #pragma unroll
    for (int i = 0; i < 8; i++) {
        int row = brow + ty * 8 + i;
        if (row >= M) continue;
        #pragma unroll
        for (int j = 0; j < 8; j++) {
            int col = bcol + tx * 8 + j;
            if (col >= N) continue;
            float v = acc[i][j];
            if (bias) v += __ldg(bias + col);
            if (EPI == 1) v = (v > 20.f) ? v : log1pf(expf(v));          // softplus
            if (EPI == 2) v = 0.5f * v * (1.f + erff(v * 0.70710678118654752f)); // gelu
            float* cp = C + (size_t)row * ldc + col;
            if (ACC) v += *cp;
            *cp = v;
        }
    }
}

// ---------------- depthwise causal conv (DCONV=4) + silu ----------------
__global__ void conv_silu_kernel(const float* __restrict__ proj,
                                 const float* __restrict__ w,
                                 float* __restrict__ u)
{
    int idx = blockIdx.x * 256 + threadIdx.x;   // over TT*DD
    int d = idx & (DD - 1);
    int t = idx >> 9;
    int l = t & (LL - 1);
    const float* wd = w + d * 4;
    float acc = 0.f;
    #pragma unroll
    for (int k = 0; k < 4; k++) {
        int ll = l - 3 + k;
        if (ll >= 0) acc = fmaf(proj[(size_t)(t - 3 + k) * PW + d], wd[k], acc);
    }
    u[idx] = acc / (1.0f + expf(-acc));   // silu
}

// ---------------- selective-scan (sequential over L, parallel over b,d) ----------------
__global__ __launch_bounds__(128) void scan_kernel(const float* __restrict__ proj,
                                                   const float* __restrict__ dt,
                                                   const float* __restrict__ u,
                                                   const float* __restrict__ Dp,
                                                   float* __restrict__ y)
{
    // 8 blocks: b = blockIdx.x>>2, d-block = blockIdx.x&3 (128 d's each)
    const int b  = blockIdx.x >> 2;
    const int d  = (blockIdx.x & 3) * 128 + threadIdx.x;
    const float dval = Dp[d];

    __shared__ float Bs[32][NSt];
    __shared__ float Cs[32][NSt];

    float h[NSt];
    #pragma unroll
    for (int n = 0; n < NSt; n++) h[n] = 0.f;

    for (int l0 = 0; l0 < LL; l0 += 32) {
        __syncthreads();
        for (int idx = threadIdx.x; idx < 32 * NSt; idx += 128) {
            int s = idx >> 4, n = idx & 15;
            const float* row = proj + (size_t)(b * LL + l0 + s) * PW;
            Bs[s][n] = row[2 * DD + RR + n];
            Cs[s][n] = row[2 * DD + RR + NSt + n];
        }
        __syncthreads();

        for (int s = 0; s < 32; s++) {
            int t = b * LL + l0 + s;
            float dtv = dt[(size_t)t * DD + d];
            float uv  = u [(size_t)t * DD + d];
            float zv  = proj[(size_t)t * PW + DD + d];
            float e = __expf(-dtv);       // a_n = e^(n+1) = exp(-dt*(n+1))
            float a = 1.f, yv = 0.f;
            #pragma unroll
            for (int n = 0; n < NSt; n++) {
                a *= e;
                const float inv = -1.0f / (float)(n + 1);   // 1/(A + 1e-10) rounds to this
                float bu = (a - 1.f) * inv * Bs[s][n] * uv;
                h[n] = fmaf(a, h[n], bu);
                yv = fmaf(Cs[s][n], h[n], yv);
            }
            float sz = zv / (1.0f + __expf(-zv));   // silu(z)
            y[(size_t)t * DD + d] = (yv + uv * dval) * sz;
        }
    }
}

// ---------------- host-side GEMM dispatcher ----------------
static inline void gemm(const float* A, int lda, const float* W, int ldw,
                        const float* bias, float* C, int ldc,
                        int M, int N, int K, int epi, bool acc)
{
    dim3 grid((N + 127) / 128, (M + 127) / 128);
    if (epi == 0 && !acc)      gemm_kernel<0, false><<<grid, 256>>>(A, lda, W, ldw, bias, C, ldc, M, N, K);
    else if (epi == 0 && acc)  gemm_kernel<0, true ><<<grid, 256>>>(A, lda, W, ldw, bias, C, ldc, M, N, K);
    else if (epi == 1)         gemm_kernel<1, false><<<grid, 256>>>(A, lda, W, ldw, bias, C, ldc, M, N, K);
    else                       gemm_kernel<2, false><<<grid, 256>>>(A, lda, W, ldw, bias, C, ldc, M, N, K);
}

// ---------------- entry point ----------------
extern "C" void kernel_launch(void* const* d_in, const int* in_sizes, int n_in,
                              void* d_out, int out_size)
{
    const int*   x_t     = (const int*)  d_in[0];
    const int*   t_in    = (const int*)  d_in[1];
    const float* tok_emb = (const float*)d_in[2];
    const float* tmlp_w1 = (const float*)d_in[3];
    const float* tmlp_b1 = (const float*)d_in[4];
    const float* tmlp_w2 = (const float*)d_in[5];
    const float* tmlp_b2 = (const float*)d_in[6];
    const float* ln1_g   = (const float*)d_in[7];
    const float* ln1_b   = (const float*)d_in[8];
    const float* in_w    = (const float*)d_in[9];
    const float* conv_w  = (const float*)d_in[10];
    const float* dt_w    = (const float*)d_in[11];
    const float* dt_b    = (const float*)d_in[12];
    const float* D_p     = (const float*)d_in[13];
    const float* out_w   = (const float*)d_in[14];
    const float* ln2_g   = (const float*)d_in[15];
    const float* ln2_b   = (const float*)d_in[16];
    const float* mlp_w1  = (const float*)d_in[17];
    const float* mlp_b1  = (const float*)d_in[18];
    const float* mlp_w2  = (const float*)d_in[19];
    const float* mlp_b2  = (const float*)d_in[20];
    const float* lno_g   = (const float*)d_in[21];
    const float* lno_b   = (const float*)d_in[22];
    const float* head_w  = (const float*)d_in[23];
    const float* head_b  = (const float*)d_in[24];
    float* out = (float*)d_out;

    float *x, *ln, *proj, *u, *dtb, *y, *ff, *te;
    cudaGetSymbolAddress((void**)&x,    g_x);
    cudaGetSymbolAddress((void**)&ln,   g_ln);
    cudaGetSymbolAddress((void**)&proj, g_proj);
    cudaGetSymbolAddress((void**)&u,    g_u);
    cudaGetSymbolAddress((void**)&dtb,  g_dt);
    cudaGetSymbolAddress((void**)&y,    g_y);
    cudaGetSymbolAddress((void**)&ff,   g_ff);
    cudaGetSymbolAddress((void**)&te,   g_te);

    te_kernel<<<BB, 256>>>(t_in, tmlp_w1, tmlp_b1, tmlp_w2, tmlp_b2, te);
    embed_kernel<<<TT * DD / 256, 256>>>(x_t, tok_emb, te, x);

    for (int i = 0; i < DEPTH; i++) {
        ln_kernel<<<TT, 256>>>(x, ln1_g + i * DD, ln1_b + i * DD, ln);
        gemm(ln, DD, in_w + (size_t)i * PW * DD, DD, nullptr,
             proj, PW, TT, PW, DD, 0, false);
        conv_silu_kernel<<<TT * DD / 256, 256>>>(proj, conv_w + (size_t)i * DD * 4, u);
        gemm(proj + 2 * DD, PW, dt_w + (size_t)i * DD * RR, RR, dt_b + i * DD,
             dtb, DD, TT, DD, RR, 1, false);
        scan_kernel<<<8, 128>>>(proj, dtb, u, D_p + i * DD, y);
        gemm(y, DD, out_w + (size_t)i * DD * DD, DD, nullptr,
             x, DD, TT, DD, DD, 0, true);
        ln_kernel<<<TT, 256>>>(x, ln2_g + i * DD, ln2_b + i * DD, ln);
        gemm(ln, DD, mlp_w1 + (size_t)i * DFF * DD, DD, mlp_b1 + i * DFF,
             ff, DFF, TT, DFF, DD, 2, false);
        gemm(ff, DFF, mlp_w2 + (size_t)i * DD * DFF, DFF, mlp_b2 + i * DD,
             x, DD, TT, DD, DFF, 0, true);
    }

    ln_kernel<<<TT, 256>>>(x, lno_g, lno_b, ln);
    gemm(ln, DD, head_w, DD, head_b, out, VOC, TT, VOC, DD, 0, false);
}

// round 2
// speedup vs baseline: 1.7205x; 1.7205x over previous
#include <cuda_runtime.h>
#include <math.h>
#include <stdint.h>

// ---------------- problem constants ----------------
#define TT    2048        // B*L tokens
#define BB    2
#define LL    1024
#define DD    512
#define NSt   16
#define RR    32
#define PW    1088        // 2D + R + 2N
#define DFF   2048
#define VOC   50000
#define DEPTH 6

// ---------------- device scratch (no allocs allowed) ----------------
__device__ float g_x   [TT * DD];
__device__ float g_ln  [TT * DD];
__device__ float g_proj[TT * PW];
__device__ float g_u   [TT * DD];
__device__ float g_dt  [TT * DD];
__device__ float g_y   [TT * DD];
__device__ float g_ff  [TT * DFF];
__device__ float g_te  [BB * DD];

// ---------------- PTX helpers ----------------
__device__ __forceinline__ void cp_async16(void* dst, const void* src, bool pred) {
    uint32_t d = (uint32_t)__cvta_generic_to_shared(dst);
    int sz = pred ? 16 : 0;
    asm volatile("cp.async.cg.shared.global [%0], [%1], 16, %2;\n" :: "r"(d), "l"(src), "r"(sz));
}
__device__ __forceinline__ void cp_commit() { asm volatile("cp.async.commit_group;\n"); }
template <int NN>
__device__ __forceinline__ void cp_wait() { asm volatile("cp.async.wait_group %0;\n" :: "n"(NN)); }

__device__ __forceinline__ uint32_t f2tf32(float x) {
    uint32_t r;
    asm("cvt.rna.tf32.f32 %0, %1;\n" : "=r"(r) : "f"(x));
    return r;
}
__device__ __forceinline__ void mma_tf32(float c[4],
                                         uint32_t a0, uint32_t a1, uint32_t a2, uint32_t a3,
                                         uint32_t b0, uint32_t b1) {
    asm volatile(
        "mma.sync.aligned.m16n8k8.row.col.f32.tf32.tf32.f32 "
        "{%0,%1,%2,%3}, {%4,%5,%6,%7}, {%8,%9}, {%0,%1,%2,%3};\n"
        : "+f"(c[0]), "+f"(c[1]), "+f"(c[2]), "+f"(c[3])
        : "r"(a0), "r"(a1), "r"(a2), "r"(a3), "r"(b0), "r"(b1));
}

// ---------------- time-embedding MLP (tiny) ----------------
__global__ void te_kernel(const int* __restrict__ t_in,
                          const float* __restrict__ w1, const float* __restrict__ b1,
                          const float* __restrict__ w2, const float* __restrict__ b2,
                          float* __restrict__ te)
{
    int b = blockIdx.x;
    int tid = threadIdx.x;            // 256 threads
    __shared__ float s0[DD];
    __shared__ float h1[4 * DD];

    double tv = (double)t_in[b];
    {
        double f = exp((double)tid * (-9.210340371976184 / 255.0));
        double e = tv * f;
        s0[tid]       = (float)sin(e);
        s0[tid + 256] = (float)cos(e);
    }
    __syncthreads();

    for (int j = tid; j < 4 * DD; j += 256) {
        const float* wr = w1 + (size_t)j * DD;
        float acc = b1[j];
        #pragma unroll 8
        for (int k = 0; k < DD; k++) acc = fmaf(s0[k], wr[k], acc);
        h1[j] = acc / (1.0f + expf(-acc));
    }
    __syncthreads();

    for (int j = tid; j < DD; j += 256) {
        const float* wr = w2 + (size_t)j * (4 * DD);
        float acc = b2[j];
        #pragma unroll 8
        for (int k = 0; k < 4 * DD; k++) acc = fmaf(h1[k], wr[k], acc);
        te[b * DD + j] = acc;
    }
}

// ---------------- embedding gather + te add ----------------
__global__ void embed_kernel(const int* __restrict__ x_t,
                             const float* __restrict__ tok_emb,
                             const float* __restrict__ te,
                             float* __restrict__ x)
{
    int idx = blockIdx.x * 256 + threadIdx.x;
    int d = idx & (DD - 1);
    int t = idx >> 9;
    int b = t >> 10;
    int tok = x_t[t];
    x[idx] = tok_emb[(size_t)tok * DD + d] + te[b * DD + d];
}

// ---------------- LayerNorm (two-pass, per token) ----------------
__global__ __launch_bounds__(256) void ln_kernel(const float* __restrict__ x,
                                                 const float* __restrict__ g,
                                                 const float* __restrict__ bta,
                                                 float* __restrict__ o)
{
    int t = blockIdx.x;
    int tid = threadIdx.x;
    const float* row = x + (size_t)t * DD;
    float v0 = row[tid], v1 = row[tid + 256];

    __shared__ float red[8];
    __shared__ float mean_s, rstd_s;

    float s = v0 + v1;
    #pragma unroll
    for (int off = 16; off > 0; off >>= 1) s += __shfl_xor_sync(0xffffffffu, s, off);
    if ((tid & 31) == 0) red[tid >> 5] = s;
    __syncthreads();
    if (tid == 0) {
        float tot = 0.f;
        #pragma unroll
        for (int i = 0; i < 8; i++) tot += red[i];
        mean_s = tot * (1.0f / DD);
    }
    __syncthreads();
    float mu = mean_s;
    float d0 = v0 - mu, d1 = v1 - mu;
    float q = d0 * d0 + d1 * d1;
    #pragma unroll
    for (int off = 16; off > 0; off >>= 1) q += __shfl_xor_sync(0xffffffffu, q, off);
    if ((tid & 31) == 0) red[tid >> 5] = q;
    __syncthreads();
    if (tid == 0) {
        float tot = 0.f;
        #pragma unroll
        for (int i = 0; i < 8; i++) tot += red[i];
        rstd_s = rsqrtf(tot * (1.0f / DD) + 1e-5f);
    }
    __syncthreads();
    float rs = rstd_s;
    o[(size_t)t * DD + tid]       = d0 * rs * g[tid]       + bta[tid];
    o[(size_t)t * DD + tid + 256] = d1 * rs * g[tid + 256] + bta[tid + 256];
}

// ---------------- TF32 tensor-core GEMM: C[M,N] = A[M,K] @ W[N,K]^T ----------------
// BM=128, BN=64, BK=32, 128 threads (2x2 warps, 64x32 warp tile), cp.async
// double buffering, XOR-swizzled smem (conflict-free fragment LDS).
// EPI: 0 = none, 1 = softplus, 2 = exact gelu.  ACC: C += result.
template <int EPI, bool ACC>
__global__ __launch_bounds__(128) void gemm_tc_kernel(
    const float* __restrict__ A, int lda,
    const float* __restrict__ W, int ldw,
    const float* __restrict__ bias,
    float* __restrict__ C, int ldc,
    int M, int N, int K)
{
    __shared__ float As[2][128 * 32];
    __shared__ float Ws[2][64 * 32];

    const int tid  = threadIdx.x;
    const int lane = tid & 31;
    const int wid  = tid >> 5;                 // 0..3
    const int wm   = (wid >> 1) * 64;          // warp m offset
    const int wn   = (wid & 1) * 32;           // warp n offset
    const int brow = blockIdx.y * 128;
    const int bcol = blockIdx.x * 64;

    float acc[4][4][4];
    #pragma unroll
    for (int i = 0; i < 4; i++)
        #pragma unroll
        for (int j = 0; j < 4; j++)
            #pragma unroll
            for (int v = 0; v < 4; v++) acc[i][j][v] = 0.f;

    const int KT = K >> 5;   // K / 32 (all K are multiples of 32)

    // ---- tile loader (one k-tile into buffer `buf`) ----
    auto load_tile = [&](int buf, int k0) {
        // A: 128 rows x 32 floats; one row per thread, 8 x 16B chunks
        {
            int m = tid;
            const float* src = A + (size_t)(brow + m) * lda + k0;
            bool pv = (brow + m) < M;
            float* drow = &As[buf][m * 32];
            #pragma unroll
            for (int c = 0; c < 8; c++)
                cp_async16(drow + ((c ^ (m & 7)) << 2), src + c * 4, pv);
        }
        // W: 64 rows x 32 floats; 2 threads per row, 4 x 16B chunks each
        {
            int n = tid >> 1;
            int cb = (tid & 1) * 4;
            const float* src = W + (size_t)(bcol + n) * ldw + k0;
            bool pv = (bcol + n) < N;
            float* drow = &Ws[buf][n * 32];
            #pragma unroll
            for (int c = 0; c < 4; c++)
                cp_async16(drow + (((cb + c) ^ (n & 7)) << 2), src + (cb + c) * 4, pv);
        }
    };

    load_tile(0, 0);
    cp_commit();

    for (int kt = 0; kt < KT; kt++) {
        if (kt + 1 < KT) {
            load_tile((kt + 1) & 1, (kt + 1) * 32);
            cp_commit();
            cp_wait<1>();
        } else {
            cp_wait<0>();
        }
        __syncthreads();

        const float* sA = &As[kt & 1][0];
        const float* sB = &Ws[kt & 1][0];
        const int lq = lane >> 2;      // 0..7
        const int lr = lane & 3;       // 0..3

        #pragma unroll
        for (int s = 0; s < 4; s++) {
            const int ch = s * 2;      // chunk of k-base (k = s*8 + lr, chunk = k>>2)
            uint32_t af[4][4];
            #pragma unroll
            for (int mt = 0; mt < 4; mt++) {
                int m0 = wm + mt * 16 + lq;
                int m1 = m0 + 8;
                af[mt][0] = f2tf32(sA[m0 * 32 + ((ch       ^ (m0 & 7)) << 2) + lr]);
                af[mt][1] = f2tf32(sA[m1 * 32 + ((ch       ^ (m1 & 7)) << 2) + lr]);
                af[mt][2] = f2tf32(sA[m0 * 32 + (((ch + 1) ^ (m0 & 7)) << 2) + lr]);
                af[mt][3] = f2tf32(sA[m1 * 32 + (((ch + 1) ^ (m1 & 7)) << 2) + lr]);
            }
            uint32_t bf[4][2];
            #pragma unroll
            for (int nt = 0; nt < 4; nt++) {
                int n = wn + nt * 8 + lq;
                bf[nt][0] = f2tf32(sB[n * 32 + ((ch       ^ (n & 7)) << 2) + lr]);
                bf[nt][1] = f2tf32(sB[n * 32 + (((ch + 1) ^ (n & 7)) << 2) + lr]);
            }
            #pragma unroll
            for (int mt = 0; mt < 4; mt++)
                #pragma unroll
                for (int nt = 0; nt < 4; nt++)
                    mma_tf32(acc[mt][nt], af[mt][0], af[mt][1], af[mt][2], af[mt][3],
                             bf[nt][0], bf[nt][1]);
        }
        __syncthreads();
    }

    // ---- epilogue ----
    const int lq = lane >> 2;
    const int lr = lane & 3;
    #pragma unroll
    for (int mt = 0; mt < 4; mt++) {
        int r0 = brow + wm + mt * 16 + lq;   // always < M (M % 128 == 0)
        int r1 = r0 + 8;
        #pragma unroll
        for (int nt = 0; nt < 4; nt++) {
            int c = bcol + wn + nt * 8 + lr * 2;
            if (c >= N) continue;            // N even, so c+1 < N too
            float v0 = acc[mt][nt][0], v1 = acc[mt][nt][1];
            float v2 = acc[mt][nt][2], v3 = acc[mt][nt][3];
            if (bias) {
                float b0 = __ldg(bias + c), b1 = __ldg(bias + c + 1);
                v0 += b0; v1 += b1; v2 += b0; v3 += b1;
            }
            if (EPI == 1) {  // softplus
                v0 = (v0 > 20.f) ? v0 : log1pf(expf(v0));
                v1 = (v1 > 20.f) ? v1 : log1pf(expf(v1));
                v2 = (v2 > 20.f) ? v2 : log1pf(expf(v2));
                v3 = (v3 > 20.f) ? v3 : log1pf(expf(v3));
            }
            if (EPI == 2) {  // exact gelu
                const float is2 = 0.70710678118654752f;
                v0 = 0.5f * v0 * (1.f + erff(v0 * is2));
                v1 = 0.5f * v1 * (1.f + erff(v1 * is2));
                v2 = 0.5f * v2 * (1.f + erff(v2 * is2));
                v3 = 0.5f * v3 * (1.f + erff(v3 * is2));
            }
            float* p0 = C + (size_t)r0 * ldc + c;
            float* p1 = C + (size_t)r1 * ldc + c;
            if (ACC) {
                float2 o0 = *(float2*)p0, o1 = *(float2*)p1;
                v0 += o0.x; v1 += o0.y; v2 += o1.x; v3 += o1.y;
            }
            *(float2*)p0 = make_float2(v0, v1);
            *(float2*)p1 = make_float2(v2, v3);
        }
    }
}

// ---------------- depthwise causal conv (DCONV=4) + silu ----------------
__global__ void conv_silu_kernel(const float* __restrict__ proj,
                                 const float* __restrict__ w,
                                 float* __restrict__ u)
{
    int idx = blockIdx.x * 256 + threadIdx.x;
    int d = idx & (DD - 1);
    int t = idx >> 9;
    int l = t & (LL - 1);
    const float* wd = w + d * 4;
    float acc = 0.f;
    #pragma unroll
    for (int k = 0; k < 4; k++) {
        int ll = l - 3 + k;
        if (ll >= 0) acc = fmaf(proj[(size_t)(t - 3 + k) * PW + d], wd[k], acc);
    }
    u[idx] = acc / (1.0f + expf(-acc));
}

// ---------------- selective-scan (sequential over L, parallel over b,d) ----------------
__global__ __launch_bounds__(128) void scan_kernel(const float* __restrict__ proj,
                                                   const float* __restrict__ dt,
                                                   const float* __restrict__ u,
                                                   const float* __restrict__ Dp,
                                                   float* __restrict__ y)
{
    const int b  = blockIdx.x >> 2;
    const int d  = (blockIdx.x & 3) * 128 + threadIdx.x;
    const float dval = Dp[d];

    __shared__ float Bs[32][NSt];
    __shared__ float Cs[32][NSt];

    float h[NSt];
    #pragma unroll
    for (int n = 0; n < NSt; n++) h[n] = 0.f;

    for (int l0 = 0; l0 < LL; l0 += 32) {
        __syncthreads();
        for (int idx = threadIdx.x; idx < 32 * NSt; idx += 128) {
            int s = idx >> 4, n = idx & 15;
            const float* row = proj + (size_t)(b * LL + l0 + s) * PW;
            Bs[s][n] = row[2 * DD + RR + n];
            Cs[s][n] = row[2 * DD + RR + NSt + n];
        }
        __syncthreads();

        for (int s = 0; s < 32; s++) {
            int t = b * LL + l0 + s;
            float dtv = dt[(size_t)t * DD + d];
            float uv  = u [(size_t)t * DD + d];
            float zv  = proj[(size_t)t * PW + DD + d];
            float e = __expf(-dtv);
            float a = 1.f, yv = 0.f;
            #pragma unroll
            for (int n = 0; n < NSt; n++) {
                a *= e;
                const float inv = -1.0f / (float)(n + 1);
                float bu = (a - 1.f) * inv * Bs[s][n] * uv;
                h[n] = fmaf(a, h[n], bu);
                yv = fmaf(Cs[s][n], h[n], yv);
            }
            float sz = zv / (1.0f + __expf(-zv));
            y[(size_t)t * DD + d] = (yv + uv * dval) * sz;
        }
    }
}

// ---------------- host-side GEMM dispatcher ----------------
static inline void gemm(const float* A, int lda, const float* W, int ldw,
                        const float* bias, float* C, int ldc,
                        int M, int N, int K, int epi, bool acc)
{
    dim3 grid((N + 63) / 64, (M + 127) / 128);
    if (epi == 0 && !acc)      gemm_tc_kernel<0, false><<<grid, 128>>>(A, lda, W, ldw, bias, C, ldc, M, N, K);
    else if (epi == 0 && acc)  gemm_tc_kernel<0, true ><<<grid, 128>>>(A, lda, W, ldw, bias, C, ldc, M, N, K);
    else if (epi == 1)         gemm_tc_kernel<1, false><<<grid, 128>>>(A, lda, W, ldw, bias, C, ldc, M, N, K);
    else                       gemm_tc_kernel<2, false><<<grid, 128>>>(A, lda, W, ldw, bias, C, ldc, M, N, K);
}

// ---------------- entry point ----------------
extern "C" void kernel_launch(void* const* d_in, const int* in_sizes, int n_in,
                              void* d_out, int out_size)
{
    const int*   x_t     = (const int*)  d_in[0];
    const int*   t_in    = (const int*)  d_in[1];
    const float* tok_emb = (const float*)d_in[2];
    const float* tmlp_w1 = (const float*)d_in[3];
    const float* tmlp_b1 = (const float*)d_in[4];
    const float* tmlp_w2 = (const float*)d_in[5];
    const float* tmlp_b2 = (const float*)d_in[6];
    const float* ln1_g   = (const float*)d_in[7];
    const float* ln1_b   = (const float*)d_in[8];
    const float* in_w    = (const float*)d_in[9];
    const float* conv_w  = (const float*)d_in[10];
    const float* dt_w    = (const float*)d_in[11];
    const float* dt_b    = (const float*)d_in[12];
    const float* D_p     = (const float*)d_in[13];
    const float* out_w   = (const float*)d_in[14];
    const float* ln2_g   = (const float*)d_in[15];
    const float* ln2_b   = (const float*)d_in[16];
    const float* mlp_w1  = (const float*)d_in[17];
    const float* mlp_b1  = (const float*)d_in[18];
    const float* mlp_w2  = (const float*)d_in[19];
    const float* mlp_b2  = (const float*)d_in[20];
    const float* lno_g   = (const float*)d_in[21];
    const float* lno_b   = (const float*)d_in[22];
    const float* head_w  = (const float*)d_in[23];
    const float* head_b  = (const float*)d_in[24];
    float* out = (float*)d_out;

    float *x, *ln, *proj, *u, *dtb, *y, *ff, *te;
    cudaGetSymbolAddress((void**)&x,    g_x);
    cudaGetSymbolAddress((void**)&ln,   g_ln);
    cudaGetSymbolAddress((void**)&proj, g_proj);
    cudaGetSymbolAddress((void**)&u,    g_u);
    cudaGetSymbolAddress((void**)&dtb,  g_dt);
    cudaGetSymbolAddress((void**)&y,    g_y);
    cudaGetSymbolAddress((void**)&ff,   g_ff);
    cudaGetSymbolAddress((void**)&te,   g_te);

    te_kernel<<<BB, 256>>>(t_in, tmlp_w1, tmlp_b1, tmlp_w2, tmlp_b2, te);
    embed_kernel<<<TT * DD / 256, 256>>>(x_t, tok_emb, te, x);

    for (int i = 0; i < DEPTH; i++) {
        ln_kernel<<<TT, 256>>>(x, ln1_g + i * DD, ln1_b + i * DD, ln);
        gemm(ln, DD, in_w + (size_t)i * PW * DD, DD, nullptr,
             proj, PW, TT, PW, DD, 0, false);
        conv_silu_kernel<<<TT * DD / 256, 256>>>(proj, conv_w + (size_t)i * DD * 4, u);
        gemm(proj + 2 * DD, PW, dt_w + (size_t)i * DD * RR, RR, dt_b + i * DD,
             dtb, DD, TT, DD, RR, 1, false);
        scan_kernel<<<8, 128>>>(proj, dtb, u, D_p + i * DD, y);
        gemm(y, DD, out_w + (size_t)i * DD * DD, DD, nullptr,
             x, DD, TT, DD, DD, 0, true);
        ln_kernel<<<TT, 256>>>(x, ln2_g + i * DD, ln2_b + i * DD, ln);
        gemm(ln, DD, mlp_w1 + (size_t)i * DFF * DD, DD, mlp_b1 + i * DFF,
             ff, DFF, TT, DFF, DD, 2, false);
        gemm(ff, DFF, mlp_w2 + (size_t)i * DD * DFF, DFF, mlp_b2 + i * DD,
             x, DD, TT, DD, DFF, 0, true);
    }

    ln_kernel<<<TT, 256>>>(x, lno_g, lno_b, ln);
    gemm(ln, DD, head_w, DD, head_b, out, VOC, TT, VOC, DD, 0, false);
}

// round 3
// speedup vs baseline: 2.0575x; 1.1959x over previous
#include <cuda_runtime.h>
#include <math.h>
#include <stdint.h>

// ---------------- problem constants ----------------
#define TT    2048        // B*L tokens
#define BB    2
#define LL    1024
#define DD    512
#define NSt   16
#define RR    32
#define PW    1088        // 2D + R + 2N
#define DFF   2048
#define VOC   50000
#define DEPTH 6

// ---------------- device scratch (no allocs allowed) ----------------
__device__ float g_x   [TT * DD];
__device__ float g_ln  [TT * DD];
__device__ float g_proj[TT * PW];
__device__ float g_u   [TT * DD];
__device__ float g_dt  [TT * DD];
__device__ float g_y   [TT * DD];
__device__ float g_ff  [TT * DFF];
__device__ float g_te  [BB * DD];

// pre-rounded (TF32-representable) weights
#define OFF_INW  0
#define OFF_DTW  3342336       // + 6*1088*512
#define OFF_OUTW 3440640       // + 6*512*32
#define OFF_W1   5013504       // + 6*512*512
#define OFF_W2   11304960      // + 6*2048*512
#define OFF_HEAD 17596416      // + 6*2048*512
#define WTF_TOTAL 43196416     // + 50000*512
__device__ float g_wtf[WTF_TOTAL];

// ---------------- PTX helpers ----------------
__device__ __forceinline__ void cp_async16(void* dst, const void* src, bool pred) {
    uint32_t d = (uint32_t)__cvta_generic_to_shared(dst);
    int sz = pred ? 16 : 0;
    asm volatile("cp.async.cg.shared.global [%0], [%1], 16, %2;\n" :: "r"(d), "l"(src), "r"(sz));
}
__device__ __forceinline__ void cp_commit() { asm volatile("cp.async.commit_group;\n"); }
template <int NN>
__device__ __forceinline__ void cp_wait() { asm volatile("cp.async.wait_group %0;\n" :: "n"(NN)); }

__device__ __forceinline__ uint32_t f2tf32(float x) {
    uint32_t r;
    asm("cvt.rna.tf32.f32 %0, %1;\n" : "=r"(r) : "f"(x));
    return r;
}
__device__ __forceinline__ float round_tf32(float x) { return __uint_as_float(f2tf32(x)); }

__device__ __forceinline__ void mma_tf32(float c[4],
                                         uint32_t a0, uint32_t a1, uint32_t a2, uint32_t a3,
                                         uint32_t b0, uint32_t b1) {
    asm volatile(
        "mma.sync.aligned.m16n8k8.row.col.f32.tf32.tf32.f32 "
        "{%0,%1,%2,%3}, {%4,%5,%6,%7}, {%8,%9}, {%0,%1,%2,%3};\n"
        : "+f"(c[0]), "+f"(c[1]), "+f"(c[2]), "+f"(c[3])
        : "r"(a0), "r"(a1), "r"(a2), "r"(a3), "r"(b0), "r"(b1));
}

// ---------------- weight pre-rounding ----------------
__global__ void roundw_kernel(const float4* __restrict__ s, float4* __restrict__ d, int n4) {
    int i = blockIdx.x * 256 + threadIdx.x;
    if (i < n4) {
        float4 v = s[i];
        v.x = round_tf32(v.x); v.y = round_tf32(v.y);
        v.z = round_tf32(v.z); v.w = round_tf32(v.w);
        d[i] = v;
    }
}

// ---------------- time-embedding MLP (tiny) ----------------
__global__ void te_kernel(const int* __restrict__ t_in,
                          const float* __restrict__ w1, const float* __restrict__ b1,
                          const float* __restrict__ w2, const float* __restrict__ b2,
                          float* __restrict__ te)
{
    int b = blockIdx.x;
    int tid = threadIdx.x;            // 256 threads
    __shared__ float s0[DD];
    __shared__ float h1[4 * DD];

    double tv = (double)t_in[b];
    {
        double f = exp((double)tid * (-9.210340371976184 / 255.0));
        double e = tv * f;
        s0[tid]       = (float)sin(e);
        s0[tid + 256] = (float)cos(e);
    }
    __syncthreads();

    for (int j = tid; j < 4 * DD; j += 256) {
        const float* wr = w1 + (size_t)j * DD;
        float acc = b1[j];
        #pragma unroll 8
        for (int k = 0; k < DD; k++) acc = fmaf(s0[k], wr[k], acc);
        h1[j] = acc / (1.0f + expf(-acc));
    }
    __syncthreads();

    for (int j = tid; j < DD; j += 256) {
        const float* wr = w2 + (size_t)j * (4 * DD);
        float acc = b2[j];
        #pragma unroll 8
        for (int k = 0; k < 4 * DD; k++) acc = fmaf(h1[k], wr[k], acc);
        te[b * DD + j] = acc;
    }
}

// ---------------- embedding gather + te add ----------------
__global__ void embed_kernel(const int* __restrict__ x_t,
                             const float* __restrict__ tok_emb,
                             const float* __restrict__ te,
                             float* __restrict__ x)
{
    int idx = blockIdx.x * 256 + threadIdx.x;
    int d = idx & (DD - 1);
    int t = idx >> 9;
    int b = t >> 10;
    int tok = x_t[t];
    x[idx] = tok_emb[(size_t)tok * DD + d] + te[b * DD + d];
}

// ---------------- LayerNorm (two-pass, per token); output rounded to tf32 ----------------
__global__ __launch_bounds__(256) void ln_kernel(const float* __restrict__ x,
                                                 const float* __restrict__ g,
                                                 const float* __restrict__ bta,
                                                 float* __restrict__ o)
{
    int t = blockIdx.x;
    int tid = threadIdx.x;
    const float* row = x + (size_t)t * DD;
    float v0 = row[tid], v1 = row[tid + 256];

    __shared__ float red[8];
    __shared__ float mean_s, rstd_s;

    float s = v0 + v1;
    #pragma unroll
    for (int off = 16; off > 0; off >>= 1) s += __shfl_xor_sync(0xffffffffu, s, off);
    if ((tid & 31) == 0) red[tid >> 5] = s;
    __syncthreads();
    if (tid == 0) {
        float tot = 0.f;
        #pragma unroll
        for (int i = 0; i < 8; i++) tot += red[i];
        mean_s = tot * (1.0f / DD);
    }
    __syncthreads();
    float mu = mean_s;
    float d0 = v0 - mu, d1 = v1 - mu;
    float q = d0 * d0 + d1 * d1;
    #pragma unroll
    for (int off = 16; off > 0; off >>= 1) q += __shfl_xor_sync(0xffffffffu, q, off);
    if ((tid & 31) == 0) red[tid >> 5] = q;
    __syncthreads();
    if (tid == 0) {
        float tot = 0.f;
        #pragma unroll
        for (int i = 0; i < 8; i++) tot += red[i];
        rstd_s = rsqrtf(tot * (1.0f / DD) + 1e-5f);
    }
    __syncthreads();
    float rs = rstd_s;
    o[(size_t)t * DD + tid]       = round_tf32(d0 * rs * g[tid]       + bta[tid]);
    o[(size_t)t * DD + tid + 256] = round_tf32(d1 * rs * g[tid + 256] + bta[tid + 256]);
}

// ---------------- TF32 tensor-core GEMM v2: C[M,N] = A[M,K] @ W[N,K]^T ----------------
// BM=128, BN in {64,128}, BK=32, 128 threads = 4 warps (2x2), warp tile 64 x BN/2.
// Operands assumed pre-rounded to tf32 grid unless CVT_A. M % 128 == 0 assumed.
// EPI: 0 none, 1 softplus, 2 exact gelu. ACC: C += result. ROUND_OUT: round stores.
template <int BN, int EPI, bool ACC, bool CVT_A, bool ROUND_OUT>
__global__ __launch_bounds__(128) void gemm_tc2(
    const float* __restrict__ A, int lda,
    const float* __restrict__ W, int ldw,
    const float* __restrict__ bias,
    float* __restrict__ C, int ldc,
    int M, int N, int K)
{
    constexpr int NT = BN / 16;            // n-tiles per warp
    extern __shared__ float sm[];
    float* As = sm;                        // 2 * 128*32
    float* Ws = sm + 2 * 128 * 32;         // 2 * BN*32

    const int tid  = threadIdx.x;
    const int lane = tid & 31;
    const int wid  = tid >> 5;             // 0..3
    const int wm   = (wid & 1) * 64;
    const int wn   = (wid >> 1) * (BN / 2);
    const int brow = blockIdx.y * 128;
    const int bcol = blockIdx.x * BN;
    const int lq   = lane >> 2;            // 0..7
    const int lr   = lane & 3;             // 0..3

    float acc[4][NT][4];
    #pragma unroll
    for (int i = 0; i < 4; i++)
        #pragma unroll
        for (int j = 0; j < NT; j++)
            #pragma unroll
            for (int v = 0; v < 4; v++) acc[i][j][v] = 0.f;

    const int KT = K >> 5;

    auto load_tile = [&](int buf, int k0) {
        // A: 128 rows x 32 floats, one row per thread, 8 x 16B chunks
        {
            int m = tid;
            const float* src = A + (size_t)(brow + m) * lda + k0;
            float* drow = &As[buf * 4096 + m * 32];
            #pragma unroll
            for (int c = 0; c < 8; c++)
                cp_async16(drow + ((c ^ (m & 7)) << 2), src + c * 4, true);
        }
        if (BN == 128) {
            int n = tid;
            const float* src = W + (size_t)(bcol + n) * ldw + k0;
            bool pv = (bcol + n) < N;
            float* drow = &Ws[buf * (BN * 32) + n * 32];
            #pragma unroll
            for (int c = 0; c < 8; c++)
                cp_async16(drow + ((c ^ (n & 7)) << 2), src + c * 4, pv);
        } else {
            int n = tid >> 1;
            int cb = (tid & 1) * 4;
            const float* src = W + (size_t)(bcol + n) * ldw + k0;
            bool pv = (bcol + n) < N;
            float* drow = &Ws[buf * (BN * 32) + n * 32];
            #pragma unroll
            for (int c = 0; c < 4; c++)
                cp_async16(drow + (((cb + c) ^ (n & 7)) << 2), src + (cb + c) * 4, pv);
        }
    };

    load_tile(0, 0);
    cp_commit();

    for (int kt = 0; kt < KT; kt++) {
        if (kt + 1 < KT) {
            load_tile((kt + 1) & 1, (kt + 1) * 32);
            cp_commit();
            cp_wait<1>();
        } else {
            cp_wait<0>();
        }
        __syncthreads();

        const float* sA = &As[(kt & 1) * 4096];
        const float* sB = &Ws[(kt & 1) * (BN * 32)];

        #pragma unroll
        for (int s = 0; s < 4; s++) {
            const int ch = s * 2;
            uint32_t af[4][4];
            #pragma unroll
            for (int mt = 0; mt < 4; mt++) {
                int m0 = wm + mt * 16 + lq;
                int m1 = m0 + 8;
                float a0 = sA[m0 * 32 + ((ch       ^ (m0 & 7)) << 2) + lr];
                float a1 = sA[m1 * 32 + ((ch       ^ (m1 & 7)) << 2) + lr];
                float a2 = sA[m0 * 32 + (((ch + 1) ^ (m0 & 7)) << 2) + lr];
                float a3 = sA[m1 * 32 + (((ch + 1) ^ (m1 & 7)) << 2) + lr];
                if (CVT_A) {
                    af[mt][0] = f2tf32(a0); af[mt][1] = f2tf32(a1);
                    af[mt][2] = f2tf32(a2); af[mt][3] = f2tf32(a3);
                } else {
                    af[mt][0] = __float_as_uint(a0); af[mt][1] = __float_as_uint(a1);
                    af[mt][2] = __float_as_uint(a2); af[mt][3] = __float_as_uint(a3);
                }
            }
            uint32_t bf[NT][2];
            #pragma unroll
            for (int nt = 0; nt < NT; nt++) {
                int n = wn + nt * 8 + lq;
                bf[nt][0] = __float_as_uint(sB[n * 32 + ((ch       ^ (n & 7)) << 2) + lr]);
                bf[nt][1] = __float_as_uint(sB[n * 32 + (((ch + 1) ^ (n & 7)) << 2) + lr]);
            }
            #pragma unroll
            for (int mt = 0; mt < 4; mt++)
                #pragma unroll
                for (int nt = 0; nt < NT; nt++)
                    mma_tf32(acc[mt][nt], af[mt][0], af[mt][1], af[mt][2], af[mt][3],
                             bf[nt][0], bf[nt][1]);
        }
        __syncthreads();
    }

    // ---- epilogue ----
    #pragma unroll
    for (int mt = 0; mt < 4; mt++) {
        int r0 = brow + wm + mt * 16 + lq;
        int r1 = r0 + 8;
        #pragma unroll
        for (int nt = 0; nt < NT; nt++) {
            int c = bcol + wn + nt * 8 + lr * 2;
            if (c >= N) continue;
            float v0 = acc[mt][nt][0], v1 = acc[mt][nt][1];
            float v2 = acc[mt][nt][2], v3 = acc[mt][nt][3];
            if (bias) {
                float b0 = __ldg(bias + c), b1 = __ldg(bias + c + 1);
                v0 += b0; v1 += b1; v2 += b0; v3 += b1;
            }
            if (EPI == 1) {
                v0 = (v0 > 20.f) ? v0 : log1pf(expf(v0));
                v1 = (v1 > 20.f) ? v1 : log1pf(expf(v1));
                v2 = (v2 > 20.f) ? v2 : log1pf(expf(v2));
                v3 = (v3 > 20.f) ? v3 : log1pf(expf(v3));
            }
            if (EPI == 2) {
                const float is2 = 0.70710678118654752f;
                v0 = 0.5f * v0 * (1.f + erff(v0 * is2));
                v1 = 0.5f * v1 * (1.f + erff(v1 * is2));
                v2 = 0.5f * v2 * (1.f + erff(v2 * is2));
                v3 = 0.5f * v3 * (1.f + erff(v3 * is2));
            }
            float* p0 = C + (size_t)r0 * ldc + c;
            float* p1 = C + (size_t)r1 * ldc + c;
            if (ACC) {
                float2 o0 = *(float2*)p0, o1 = *(float2*)p1;
                v0 += o0.x; v1 += o0.y; v2 += o1.x; v3 += o1.y;
            }
            if (ROUND_OUT) {
                v0 = round_tf32(v0); v1 = round_tf32(v1);
                v2 = round_tf32(v2); v3 = round_tf32(v3);
            }
            *(float2*)p0 = make_float2(v0, v1);
            *(float2*)p1 = make_float2(v2, v3);
        }
    }
}

// ---------------- depthwise causal conv (DCONV=4) + silu ----------------
__global__ void conv_silu_kernel(const float* __restrict__ proj,
                                 const float* __restrict__ w,
                                 float* __restrict__ u)
{
    int idx = blockIdx.x * 256 + threadIdx.x;
    int d = idx & (DD - 1);
    int t = idx >> 9;
    int l = t & (LL - 1);
    const float* wd = w + d * 4;
    float acc = 0.f;
    #pragma unroll
    for (int k = 0; k < 4; k++) {
        int ll = l - 3 + k;
        if (ll >= 0) acc = fmaf(proj[(size_t)(t - 3 + k) * PW + d], wd[k], acc);
    }
    u[idx] = acc / (1.0f + expf(-acc));
}

// ---------------- selective-scan v2: half-warp per (b,d), lane per state ----------------
__global__ __launch_bounds__(256) void scan2_kernel(const float* __restrict__ proj,
                                                    const float* __restrict__ dt,
                                                    const float* __restrict__ u,
                                                    const float* __restrict__ Dp,
                                                    float* __restrict__ y)
{
    int hw = blockIdx.x * 16 + (threadIdx.x >> 4);  // 0..1023
    int b = hw >> 9;
    int d = hw & 511;
    int n = threadIdx.x & 15;

    const float coef = -(float)(n + 1);
    const float inv  = -1.0f / (float)(n + 1);
    const float dval = Dp[d];

    const float* projB = proj + (size_t)b * LL * PW;
    const float* dtB   = dt   + (size_t)b * LL * DD + d;
    const float* uB    = u    + (size_t)b * LL * DD + d;
    float*       yB    = y    + (size_t)b * LL * DD + d;

    float h = 0.f;
    float dtv = dtB[0];
    float uv  = uB[0];
    float zv  = projB[DD + d];
    float Bn  = projB[2 * DD + RR + n];
    float Cn  = projB[2 * DD + RR + NSt + n];

    for (int l = 0; l < LL; l++) {
        float dt2 = 0.f, u2 = 0.f, z2 = 0.f, B2 = 0.f, C2 = 0.f;
        if (l + 1 < LL) {
            dt2 = dtB[(size_t)(l + 1) * DD];
            u2  = uB [(size_t)(l + 1) * DD];
            const float* row = projB + (size_t)(l + 1) * PW;
            z2 = row[DD + d];
            B2 = row[2 * DD + RR + n];
            C2 = row[2 * DD + RR + NSt + n];
        }
        float a  = __expf(dtv * coef);           // exp(-dt*(n+1))
        float bu = (a - 1.f) * inv * Bn * uv;
        h = fmaf(a, h, bu);
        float p = Cn * h;
        p += __shfl_xor_sync(0xffffffffu, p, 8);
        p += __shfl_xor_sync(0xffffffffu, p, 4);
        p += __shfl_xor_sync(0xffffffffu, p, 2);
        p += __shfl_xor_sync(0xffffffffu, p, 1);
        if (n == 0) {
            float sz = zv / (1.f + __expf(-zv));
            yB[(size_t)l * DD] = round_tf32((p + uv * dval) * sz);
        }
        dtv = dt2; uv = u2; zv = z2; Bn = B2; Cn = C2;
    }
}

// ---------------- host-side GEMM dispatchers ----------------
#define SMEM_A_BYTES ((2 * 128 * 32 + 2 * 128 * 32) * 4)   // 65536
#define SMEM_B_BYTES ((2 * 128 * 32 + 2 * 64 * 32) * 4)    // 49152

// head / mlp1 (large N)
static inline void gemmA(const float* A, int lda, const float* W, int ldw,
                         const float* bias, float* C, int ldc,
                         int M, int N, int K, int epi, bool round_out)
{
    dim3 grid((N + 127) / 128, M / 128);
    if (epi == 0)
        gemm_tc2<128, 0, false, false, false><<<grid, 128, SMEM_A_BYTES>>>(A, lda, W, ldw, bias, C, ldc, M, N, K);
    else
        gemm_tc2<128, 2, false, false, true><<<grid, 128, SMEM_A_BYTES>>>(A, lda, W, ldw, bias, C, ldc, M, N, K);
}

// small-N GEMMs
static inline void gemmB(const float* A, int lda, const float* W, int ldw,
                         const float* bias, float* C, int ldc,
                         int M, int N, int K, int epi, bool acc, bool cvt_a)
{
    dim3 grid((N + 63) / 64, M / 128);
    if (cvt_a)
        gemm_tc2<64, 1, false, true, false><<<grid, 128, SMEM_B_BYTES>>>(A, lda, W, ldw, bias, C, ldc, M, N, K);
    else if (acc)
        gemm_tc2<64, 0, true, false, false><<<grid, 128, SMEM_B_BYTES>>>(A, lda, W, ldw, bias, C, ldc, M, N, K);
    else
        gemm_tc2<64, 0, false, false, false><<<grid, 128, SMEM_B_BYTES>>>(A, lda, W, ldw, bias, C, ldc, M, N, K);
}

// ---------------- entry point ----------------
extern "C" void kernel_launch(void* const* d_in, const int* in_sizes, int n_in,
                              void* d_out, int out_size)
{
    const int*   x_t     = (const int*)  d_in[0];
    const int*   t_in    = (const int*)  d_in[1];
    const float* tok_emb = (const float*)d_in[2];
    const float* tmlp_w1 = (const float*)d_in[3];
    const float* tmlp_b1 = (const float*)d_in[4];
    const float* tmlp_w2 = (const float*)d_in[5];
    const float* tmlp_b2 = (const float*)d_in[6];
    const float* ln1_g   = (const float*)d_in[7];
    const float* ln1_b   = (const float*)d_in[8];
    const float* in_w    = (const float*)d_in[9];
    const float* conv_w  = (const float*)d_in[10];
    const float* dt_w    = (const float*)d_in[11];
    const float* dt_b    = (const float*)d_in[12];
    const float* D_p     = (const float*)d_in[13];
    const float* out_w   = (const float*)d_in[14];
    const float* ln2_g   = (const float*)d_in[15];
    const float* ln2_b   = (const float*)d_in[16];
    const float* mlp_w1  = (const float*)d_in[17];
    const float* mlp_b1  = (const float*)d_in[18];
    const float* mlp_w2  = (const float*)d_in[19];
    const float* mlp_b2  = (const float*)d_in[20];
    const float* lno_g   = (const float*)d_in[21];
    const float* lno_b   = (const float*)d_in[22];
    const float* head_w  = (const float*)d_in[23];
    const float* head_b  = (const float*)d_in[24];
    float* out = (float*)d_out;

    float *x, *ln, *proj, *u, *dtb, *y, *ff, *te, *wtf;
    cudaGetSymbolAddress((void**)&x,    g_x);
    cudaGetSymbolAddress((void**)&ln,   g_ln);
    cudaGetSymbolAddress((void**)&proj, g_proj);
    cudaGetSymbolAddress((void**)&u,    g_u);
    cudaGetSymbolAddress((void**)&dtb,  g_dt);
    cudaGetSymbolAddress((void**)&y,    g_y);
    cudaGetSymbolAddress((void**)&ff,   g_ff);
    cudaGetSymbolAddress((void**)&te,   g_te);
    cudaGetSymbolAddress((void**)&wtf,  g_wtf);

    // raise dynamic smem limits (host API; executes immediately even under capture)
    cudaFuncSetAttribute((const void*)gemm_tc2<128, 0, false, false, false>, cudaFuncAttributeMaxDynamicSharedMemorySize, SMEM_A_BYTES);
    cudaFuncSetAttribute((const void*)gemm_tc2<128, 2, false, false, true>,  cudaFuncAttributeMaxDynamicSharedMemorySize, SMEM_A_BYTES);
    cudaFuncSetAttribute((const void*)gemm_tc2<64, 1, false, true, false>,   cudaFuncAttributeMaxDynamicSharedMemorySize, SMEM_B_BYTES);
    cudaFuncSetAttribute((const void*)gemm_tc2<64, 0, true, false, false>,   cudaFuncAttributeMaxDynamicSharedMemorySize, SMEM_B_BYTES);
    cudaFuncSetAttribute((const void*)gemm_tc2<64, 0, false, false, false>,  cudaFuncAttributeMaxDynamicSharedMemorySize, SMEM_B_BYTES);

    float* inw_t  = wtf + OFF_INW;
    float* dtw_t  = wtf + OFF_DTW;
    float* outw_t = wtf + OFF_OUTW;
    float* w1_t   = wtf + OFF_W1;
    float* w2_t   = wtf + OFF_W2;
    float* head_t = wtf + OFF_HEAD;

    // pre-round all GEMM weights to the tf32 grid (once per call)
    {
        int n;
        n = DEPTH * PW * DD / 4;   roundw_kernel<<<(n + 255) / 256, 256>>>((const float4*)in_w,   (float4*)inw_t,  n);
        n = DEPTH * DD * RR / 4;   roundw_kernel<<<(n + 255) / 256, 256>>>((const float4*)dt_w,   (float4*)dtw_t,  n);
        n = DEPTH * DD * DD / 4;   roundw_kernel<<<(n + 255) / 256, 256>>>((const float4*)out_w,  (float4*)outw_t, n);
        n = DEPTH * DFF * DD / 4;  roundw_kernel<<<(n + 255) / 256, 256>>>((const float4*)mlp_w1, (float4*)w1_t,   n);
        n = DEPTH * DD * DFF / 4;  roundw_kernel<<<(n + 255) / 256, 256>>>((const float4*)mlp_w2, (float4*)w2_t,   n);
        n = VOC * DD / 4;          roundw_kernel<<<(n + 255) / 256, 256>>>((const float4*)head_w, (float4*)head_t, n);
    }

    te_kernel<<<BB, 256>>>(t_in, tmlp_w1, tmlp_b1, tmlp_w2, tmlp_b2, te);
    embed_kernel<<<TT * DD / 256, 256>>>(x_t, tok_emb, te, x);

    for (int i = 0; i < DEPTH; i++) {
        ln_kernel<<<TT, 256>>>(x, ln1_g + i * DD, ln1_b + i * DD, ln);
        gemmB(ln, DD, inw_t + (size_t)i * PW * DD, DD, nullptr,
              proj, PW, TT, PW, DD, 0, false, false);
        conv_silu_kernel<<<TT * DD / 256, 256>>>(proj, conv_w + (size_t)i * DD * 4, u);
        gemmB(proj + 2 * DD, PW, dtw_t + (size_t)i * DD * RR, RR, dt_b + i * DD,
              dtb, DD, TT, DD, RR, 1, false, true);
        scan2_kernel<<<64, 256>>>(proj, dtb, u, D_p + i * DD, y);
        gemmB(y, DD, outw_t + (size_t)i * DD * DD, DD, nullptr,
              x, DD, TT, DD, DD, 0, true, false);
        ln_kernel<<<TT, 256>>>(x, ln2_g + i * DD, ln2_b + i * DD, ln);
        gemmA(ln, DD, w1_t + (size_t)i * DFF * DD, DD, mlp_b1 + i * DFF,
              ff, DFF, TT, DFF, DD, 2, true);
        gemmB(ff, DFF, w2_t + (size_t)i * DD * DFF, DFF, mlp_b2 + i * DD,
              x, DD, TT, DD, DFF, 0, true, false);
    }

    ln_kernel<<<TT, 256>>>(x, lno_g, lno_b, ln);
    gemmA(ln, DD, head_t, DD, head_b, out, VOC, TT, VOC, DD, 0, false);
}

// round 4
// speedup vs baseline: 2.9078x; 1.4133x over previous
#include <cuda_runtime.h>
#include <math.h>
#include <stdint.h>

// ---------------- problem constants ----------------
#define TT    2048        // B*L tokens
#define BB    2
#define LL    1024
#define DD    512
#define NSt   16
#define RR    32
#define PW    1088        // 2D + R + 2N
#define DFF   2048
#define VOC   50000
#define DEPTH 6
#define NCH   8           // scan chunks
#define CHL   128         // chunk length

// ---------------- device scratch (no allocs allowed) ----------------
__device__ float g_x   [TT * DD];
__device__ float g_ln  [TT * DD];
__device__ float g_proj[TT * PW];
__device__ float g_u   [TT * DD];
__device__ float g_dt  [TT * DD];
__device__ float g_y   [TT * DD];
__device__ float g_ff  [TT * DFF];
__device__ float g_te  [BB * DD];
__device__ float g_scanP [NCH * BB * DD * NSt];
__device__ float g_scanS [NCH * BB * DD * NSt];
__device__ float g_scanH0[NCH * BB * DD * NSt];

// pre-rounded (TF32-representable) weights
#define OFF_INW  0
#define OFF_DTW  3342336       // + 6*1088*512
#define OFF_OUTW 3440640       // + 6*512*32
#define OFF_W1   5013504       // + 6*512*512
#define OFF_W2   11304960      // + 6*2048*512
#define OFF_HEAD 17596416      // + 6*2048*512
#define WTF_TOTAL 43196416     // + 50000*512
__device__ float g_wtf[WTF_TOTAL];

// ---------------- PTX helpers ----------------
__device__ __forceinline__ void cp_async16(void* dst, const void* src, bool pred) {
    uint32_t d = (uint32_t)__cvta_generic_to_shared(dst);
    int sz = pred ? 16 : 0;
    asm volatile("cp.async.cg.shared.global [%0], [%1], 16, %2;\n" :: "r"(d), "l"(src), "r"(sz));
}
__device__ __forceinline__ void cp_commit() { asm volatile("cp.async.commit_group;\n"); }
template <int NN>
__device__ __forceinline__ void cp_wait() { asm volatile("cp.async.wait_group %0;\n" :: "n"(NN)); }

__device__ __forceinline__ uint32_t f2tf32(float x) {
    uint32_t r;
    asm("cvt.rna.tf32.f32 %0, %1;\n" : "=r"(r) : "f"(x));
    return r;
}
__device__ __forceinline__ float round_tf32(float x) { return __uint_as_float(f2tf32(x)); }

__device__ __forceinline__ void mma_tf32(float c[4],
                                         uint32_t a0, uint32_t a1, uint32_t a2, uint32_t a3,
                                         uint32_t b0, uint32_t b1) {
    asm volatile(
        "mma.sync.aligned.m16n8k8.row.col.f32.tf32.tf32.f32 "
        "{%0,%1,%2,%3}, {%4,%5,%6,%7}, {%8,%9}, {%0,%1,%2,%3};\n"
        : "+f"(c[0]), "+f"(c[1]), "+f"(c[2]), "+f"(c[3])
        : "r"(a0), "r"(a1), "r"(a2), "r"(a3), "r"(b0), "r"(b1));
}

// ---------------- weight pre-rounding ----------------
__global__ void roundw_kernel(const float4* __restrict__ s, float4* __restrict__ d, int n4) {
    int i = blockIdx.x * 256 + threadIdx.x;
    if (i < n4) {
        float4 v = s[i];
        v.x = round_tf32(v.x); v.y = round_tf32(v.y);
        v.z = round_tf32(v.z); v.w = round_tf32(v.w);
        d[i] = v;
    }
}

// ---------------- time-embedding MLP (tiny) ----------------
__global__ void te_kernel(const int* __restrict__ t_in,
                          const float* __restrict__ w1, const float* __restrict__ b1,
                          const float* __restrict__ w2, const float* __restrict__ b2,
                          float* __restrict__ te)
{
    int b = blockIdx.x;
    int tid = threadIdx.x;            // 256 threads
    __shared__ float s0[DD];
    __shared__ float h1[4 * DD];

    double tv = (double)t_in[b];
    {
        double f = exp((double)tid * (-9.210340371976184 / 255.0));
        double e = tv * f;
        s0[tid]       = (float)sin(e);
        s0[tid + 256] = (float)cos(e);
    }
    __syncthreads();

    for (int j = tid; j < 4 * DD; j += 256) {
        const float* wr = w1 + (size_t)j * DD;
        float acc = b1[j];
        #pragma unroll 8
        for (int k = 0; k < DD; k++) acc = fmaf(s0[k], wr[k], acc);
        h1[j] = acc / (1.0f + expf(-acc));
    }
    __syncthreads();

    for (int j = tid; j < DD; j += 256) {
        const float* wr = w2 + (size_t)j * (4 * DD);
        float acc = b2[j];
        #pragma unroll 8
        for (int k = 0; k < 4 * DD; k++) acc = fmaf(h1[k], wr[k], acc);
        te[b * DD + j] = acc;
    }
}

// ---------------- embedding gather + te add ----------------
__global__ void embed_kernel(const int* __restrict__ x_t,
                             const float* __restrict__ tok_emb,
                             const float* __restrict__ te,
                             float* __restrict__ x)
{
    int idx = blockIdx.x * 256 + threadIdx.x;
    int d = idx & (DD - 1);
    int t = idx >> 9;
    int b = t >> 10;
    int tok = x_t[t];
    x[idx] = tok_emb[(size_t)tok * DD + d] + te[b * DD + d];
}

// ---------------- LayerNorm (two-pass, per token); output rounded to tf32 ----------------
__global__ __launch_bounds__(256) void ln_kernel(const float* __restrict__ x,
                                                 const float* __restrict__ g,
                                                 const float* __restrict__ bta,
                                                 float* __restrict__ o)
{
    int t = blockIdx.x;
    int tid = threadIdx.x;
    const float* row = x + (size_t)t * DD;
    float v0 = row[tid], v1 = row[tid + 256];

    __shared__ float red[8];
    __shared__ float mean_s, rstd_s;

    float s = v0 + v1;
    #pragma unroll
    for (int off = 16; off > 0; off >>= 1) s += __shfl_xor_sync(0xffffffffu, s, off);
    if ((tid & 31) == 0) red[tid >> 5] = s;
    __syncthreads();
    if (tid == 0) {
        float tot = 0.f;
        #pragma unroll
        for (int i = 0; i < 8; i++) tot += red[i];
        mean_s = tot * (1.0f / DD);
    }
    __syncthreads();
    float mu = mean_s;
    float d0 = v0 - mu, d1 = v1 - mu;
    float q = d0 * d0 + d1 * d1;
    #pragma unroll
    for (int off = 16; off > 0; off >>= 1) q += __shfl_xor_sync(0xffffffffu, q, off);
    if ((tid & 31) == 0) red[tid >> 5] = q;
    __syncthreads();
    if (tid == 0) {
        float tot = 0.f;
        #pragma unroll
        for (int i = 0; i < 8; i++) tot += red[i];
        rstd_s = rsqrtf(tot * (1.0f / DD) + 1e-5f);
    }
    __syncthreads();
    float rs = rstd_s;
    o[(size_t)t * DD + tid]       = round_tf32(d0 * rs * g[tid]       + bta[tid]);
    o[(size_t)t * DD + tid + 256] = round_tf32(d1 * rs * g[tid + 256] + bta[tid + 256]);
}

// ---------------- TF32 tensor-core GEMM v3: C[M,N] = A[M,K] @ W[N,K]^T ----------------
// BM in {64,128}, BN in {64,128}, BK=32, 128 threads = 4 warps (2x2),
// warp tile (BM/2) x (BN/2). M % BM == 0 assumed. Weights pre-rounded to tf32.
// EPI: 0 none, 1 softplus, 2 exact gelu. ACC: C += result. ROUND_OUT: round stores.
template <int BM, int BN, int EPI, bool ACC, bool CVT_A, bool ROUND_OUT>
__global__ __launch_bounds__(128) void gemm_tc2(
    const float* __restrict__ A, int lda,
    const float* __restrict__ W, int ldw,
    const float* __restrict__ bias,
    float* __restrict__ C, int ldc,
    int M, int N, int K)
{
    constexpr int MT = BM / 32;            // m-tiles (16 rows) per warp
    constexpr int NT = BN / 16;            // n-tiles (8 cols) per warp
    extern __shared__ float sm[];
    float* As = sm;                        // 2 * BM*32
    float* Ws = sm + 2 * BM * 32;          // 2 * BN*32

    const int tid  = threadIdx.x;
    const int lane = tid & 31;
    const int wid  = tid >> 5;             // 0..3
    const int wm   = (wid & 1) * (BM / 2);
    const int wn   = (wid >> 1) * (BN / 2);
    const int brow = blockIdx.y * BM;
    const int bcol = blockIdx.x * BN;
    const int lq   = lane >> 2;            // 0..7
    const int lr   = lane & 3;             // 0..3

    float acc[MT][NT][4];
    #pragma unroll
    for (int i = 0; i < MT; i++)
        #pragma unroll
        for (int j = 0; j < NT; j++)
            #pragma unroll
            for (int v = 0; v < 4; v++) acc[i][j][v] = 0.f;

    const int KT = K >> 5;

    auto load_tile = [&](int buf, int k0) {
        if (BM == 128) {
            int m = tid;
            const float* src = A + (size_t)(brow + m) * lda + k0;
            float* drow = &As[buf * (BM * 32) + m * 32];
            #pragma unroll
            for (int c = 0; c < 8; c++)
                cp_async16(drow + ((c ^ (m & 7)) << 2), src + c * 4, true);
        } else {
            int m = tid >> 1;
            int cb = (tid & 1) * 4;
            const float* src = A + (size_t)(brow + m) * lda + k0;
            float* drow = &As[buf * (BM * 32) + m * 32];
            #pragma unroll
            for (int c = 0; c < 4; c++)
                cp_async16(drow + (((cb + c) ^ (m & 7)) << 2), src + (cb + c) * 4, true);
        }
        if (BN == 128) {
            int n = tid;
            const float* src = W + (size_t)(bcol + n) * ldw + k0;
            bool pv = (bcol + n) < N;
            float* drow = &Ws[buf * (BN * 32) + n * 32];
            #pragma unroll
            for (int c = 0; c < 8; c++)
                cp_async16(drow + ((c ^ (n & 7)) << 2), src + c * 4, pv);
        } else {
            int n = tid >> 1;
            int cb = (tid & 1) * 4;
            const float* src = W + (size_t)(bcol + n) * ldw + k0;
            bool pv = (bcol + n) < N;
            float* drow = &Ws[buf * (BN * 32) + n * 32];
            #pragma unroll
            for (int c = 0; c < 4; c++)
                cp_async16(drow + (((cb + c) ^ (n & 7)) << 2), src + (cb + c) * 4, pv);
        }
    };

    load_tile(0, 0);
    cp_commit();

    for (int kt = 0; kt < KT; kt++) {
        if (kt + 1 < KT) {
            load_tile((kt + 1) & 1, (kt + 1) * 32);
            cp_commit();
            cp_wait<1>();
        } else {
            cp_wait<0>();
        }
        __syncthreads();

        const float* sA = &As[(kt & 1) * (BM * 32)];
        const float* sB = &Ws[(kt & 1) * (BN * 32)];

        #pragma unroll
        for (int s = 0; s < 4; s++) {
            const int ch = s * 2;
            uint32_t af[MT][4];
            #pragma unroll
            for (int mt = 0; mt < MT; mt++) {
                int m0 = wm + mt * 16 + lq;
                int m1 = m0 + 8;
                float a0 = sA[m0 * 32 + ((ch       ^ (m0 & 7)) << 2) + lr];
                float a1 = sA[m1 * 32 + ((ch       ^ (m1 & 7)) << 2) + lr];
                float a2 = sA[m0 * 32 + (((ch + 1) ^ (m0 & 7)) << 2) + lr];
                float a3 = sA[m1 * 32 + (((ch + 1) ^ (m1 & 7)) << 2) + lr];
                if (CVT_A) {
                    af[mt][0] = f2tf32(a0); af[mt][1] = f2tf32(a1);
                    af[mt][2] = f2tf32(a2); af[mt][3] = f2tf32(a3);
                } else {
                    af[mt][0] = __float_as_uint(a0); af[mt][1] = __float_as_uint(a1);
                    af[mt][2] = __float_as_uint(a2); af[mt][3] = __float_as_uint(a3);
                }
            }
            uint32_t bf[NT][2];
            #pragma unroll
            for (int nt = 0; nt < NT; nt++) {
                int n = wn + nt * 8 + lq;
                bf[nt][0] = __float_as_uint(sB[n * 32 + ((ch       ^ (n & 7)) << 2) + lr]);
                bf[nt][1] = __float_as_uint(sB[n * 32 + (((ch + 1) ^ (n & 7)) << 2) + lr]);
            }
            #pragma unroll
            for (int mt = 0; mt < MT; mt++)
                #pragma unroll
                for (int nt = 0; nt < NT; nt++)
                    mma_tf32(acc[mt][nt], af[mt][0], af[mt][1], af[mt][2], af[mt][3],
                             bf[nt][0], bf[nt][1]);
        }
        __syncthreads();
    }

    // ---- epilogue ----
    #pragma unroll
    for (int mt = 0; mt < MT; mt++) {
        int r0 = brow + wm + mt * 16 + lq;
        int r1 = r0 + 8;
        #pragma unroll
        for (int nt = 0; nt < NT; nt++) {
            int c = bcol + wn + nt * 8 + lr * 2;
            if (c >= N) continue;
            float v0 = acc[mt][nt][0], v1 = acc[mt][nt][1];
            float v2 = acc[mt][nt][2], v3 = acc[mt][nt][3];
            if (bias) {
                float b0 = __ldg(bias + c), b1 = __ldg(bias + c + 1);
                v0 += b0; v1 += b1; v2 += b0; v3 += b1;
            }
            if (EPI == 1) {
                v0 = (v0 > 20.f) ? v0 : log1pf(expf(v0));
                v1 = (v1 > 20.f) ? v1 : log1pf(expf(v1));
                v2 = (v2 > 20.f) ? v2 : log1pf(expf(v2));
                v3 = (v3 > 20.f) ? v3 : log1pf(expf(v3));
            }
            if (EPI == 2) {
                const float is2 = 0.70710678118654752f;
                v0 = 0.5f * v0 * (1.f + erff(v0 * is2));
                v1 = 0.5f * v1 * (1.f + erff(v1 * is2));
                v2 = 0.5f * v2 * (1.f + erff(v2 * is2));
                v3 = 0.5f * v3 * (1.f + erff(v3 * is2));
            }
            float* p0 = C + (size_t)r0 * ldc + c;
            float* p1 = C + (size_t)r1 * ldc + c;
            if (ACC) {
                float2 o0 = *(float2*)p0, o1 = *(float2*)p1;
                v0 += o0.x; v1 += o0.y; v2 += o1.x; v3 += o1.y;
            }
            if (ROUND_OUT) {
                v0 = round_tf32(v0); v1 = round_tf32(v1);
                v2 = round_tf32(v2); v3 = round_tf32(v3);
            }
            *(float2*)p0 = make_float2(v0, v1);
            *(float2*)p1 = make_float2(v2, v3);
        }
    }
}

// ---------------- depthwise causal conv (DCONV=4) + silu ----------------
__global__ void conv_silu_kernel(const float* __restrict__ proj,
                                 const float* __restrict__ w,
                                 float* __restrict__ u)
{
    int idx = blockIdx.x * 256 + threadIdx.x;
    int d = idx & (DD - 1);
    int t = idx >> 9;
    int l = t & (LL - 1);
    const float* wd = w + d * 4;
    float acc = 0.f;
    #pragma unroll
    for (int k = 0; k < 4; k++) {
        int ll = l - 3 + k;
        if (ll >= 0) acc = fmaf(proj[(size_t)(t - 3 + k) * PW + d], wd[k], acc);
    }
    u[idx] = acc / (1.0f + expf(-acc));
}

// ---------------- chunked selective-scan ----------------
// Pass 1: per chunk, local scan from h=0; emit P = prod(a) and S = local final h.
__global__ __launch_bounds__(256) void scan_p1(const float* __restrict__ proj,
                                               const float* __restrict__ dt,
                                               const float* __restrict__ u,
                                               float* __restrict__ P,
                                               float* __restrict__ S)
{
    int idx = blockIdx.x * 256 + threadIdx.x;     // over NCH*BB*DD*NSt
    int n  = idx & 15;
    int hw = idx >> 4;                            // c*(BB*DD) + b*DD + d
    int c  = hw >> 10;
    int b  = (hw >> 9) & 1;
    int d  = hw & 511;

    const float coef = -(float)(n + 1);
    const float inv  = -1.0f / (float)(n + 1);
    int t0 = b * LL + c * CHL;

    const float* dtP = dt + (size_t)t0 * DD + d;
    const float* uP  = u  + (size_t)t0 * DD + d;
    const float* BP  = proj + (size_t)t0 * PW + 2 * DD + RR + n;

    float Pr = 1.f, h = 0.f;
    float dtv = dtP[0], uv = uP[0], Bn = BP[0];
    for (int l = 0; l < CHL; l++) {
        float dt2 = 0.f, u2 = 0.f, B2 = 0.f;
        if (l + 1 < CHL) {
            dt2 = dtP[(size_t)(l + 1) * DD];
            u2  = uP [(size_t)(l + 1) * DD];
            B2  = BP [(size_t)(l + 1) * PW];
        }
        float a = __expf(dtv * coef);
        Pr *= a;
        h = fmaf(a, h, (a - 1.f) * inv * Bn * uv);
        dtv = dt2; uv = u2; Bn = B2;
    }
    P[idx] = Pr;
    S[idx] = h;
}

// Pass 2: serial recombine over chunks -> chunk-initial states h0.
__global__ __launch_bounds__(256) void scan_p2(const float* __restrict__ P,
                                               const float* __restrict__ S,
                                               float* __restrict__ h0)
{
    int idx = blockIdx.x * 256 + threadIdx.x;     // over BB*DD*NSt = 16384
    float H = 0.f;
    #pragma unroll
    for (int c = 0; c < NCH; c++) {
        int off = c * (BB * DD * NSt) + idx;
        h0[off] = H;
        H = fmaf(P[off], H, S[off]);
    }
}

// Pass 3: per chunk, scan from h0 and emit y.
__global__ __launch_bounds__(256) void scan_p3(const float* __restrict__ proj,
                                               const float* __restrict__ dt,
                                               const float* __restrict__ u,
                                               const float* __restrict__ Dp,
                                               const float* __restrict__ h0,
                                               float* __restrict__ y)
{
    int idx = blockIdx.x * 256 + threadIdx.x;
    int n  = idx & 15;
    int hw = idx >> 4;
    int c  = hw >> 10;
    int b  = (hw >> 9) & 1;
    int d  = hw & 511;

    const float coef = -(float)(n + 1);
    const float inv  = -1.0f / (float)(n + 1);
    const float dval = Dp[d];
    int t0 = b * LL + c * CHL;

    const float* dtP = dt + (size_t)t0 * DD + d;
    const float* uP  = u  + (size_t)t0 * DD + d;
    const float* rowP = proj + (size_t)t0 * PW;
    float*       yP  = y  + (size_t)t0 * DD + d;

    float h = h0[idx];
    float dtv = dtP[0];
    float uv  = uP[0];
    float zv  = rowP[DD + d];
    float Bn  = rowP[2 * DD + RR + n];
    float Cn  = rowP[2 * DD + RR + NSt + n];

    for (int l = 0; l < CHL; l++) {
        float dt2 = 0.f, u2 = 0.f, z2 = 0.f, B2 = 0.f, C2 = 0.f;
        if (l + 1 < CHL) {
            dt2 = dtP[(size_t)(l + 1) * DD];
            u2  = uP [(size_t)(l + 1) * DD];
            const float* row = rowP + (size_t)(l + 1) * PW;
            z2 = row[DD + d];
            B2 = row[2 * DD + RR + n];
            C2 = row[2 * DD + RR + NSt + n];
        }
        float a  = __expf(dtv * coef);
        h = fmaf(a, h, (a - 1.f) * inv * Bn * uv);
        float p = Cn * h;
        p += __shfl_xor_sync(0xffffffffu, p, 8);
        p += __shfl_xor_sync(0xffffffffu, p, 4);
        p += __shfl_xor_sync(0xffffffffu, p, 2);
        p += __shfl_xor_sync(0xffffffffu, p, 1);
        if (n == 0) {
            float sz = zv / (1.f + __expf(-zv));
            yP[(size_t)l * DD] = round_tf32((p + uv * dval) * sz);
        }
        dtv = dt2; uv = u2; zv = z2; Bn = B2; Cn = C2;
    }
}

// ---------------- host-side GEMM dispatch ----------------
template <int BM, int BN, int EPI, bool ACC, bool CVT_A, bool RO>
static inline void launch_gemm(const float* A, int lda, const float* W, int ldw,
                               const float* bias, float* C, int ldc,
                               int M, int N, int K)
{
    dim3 grid((N + BN - 1) / BN, M / BM);
    size_t smem = (size_t)(2 * BM * 32 + 2 * BN * 32) * 4;
    gemm_tc2<BM, BN, EPI, ACC, CVT_A, RO><<<grid, 128, smem>>>(A, lda, W, ldw, bias, C, ldc, M, N, K);
}

// ---------------- entry point ----------------
extern "C" void kernel_launch(void* const* d_in, const int* in_sizes, int n_in,
                              void* d_out, int out_size)
{
    const int*   x_t     = (const int*)  d_in[0];
    const int*   t_in    = (const int*)  d_in[1];
    const float* tok_emb = (const float*)d_in[2];
    const float* tmlp_w1 = (const float*)d_in[3];
    const float* tmlp_b1 = (const float*)d_in[4];
    const float* tmlp_w2 = (const float*)d_in[5];
    const float* tmlp_b2 = (const float*)d_in[6];
    const float* ln1_g   = (const float*)d_in[7];
    const float* ln1_b   = (const float*)d_in[8];
    const float* in_w    = (const float*)d_in[9];
    const float* conv_w  = (const float*)d_in[10];
    const float* dt_w    = (const float*)d_in[11];
    const float* dt_b    = (const float*)d_in[12];
    const float* D_p     = (const float*)d_in[13];
    const float* out_w   = (const float*)d_in[14];
    const float* ln2_g   = (const float*)d_in[15];
    const float* ln2_b   = (const float*)d_in[16];
    const float* mlp_w1  = (const float*)d_in[17];
    const float* mlp_b1  = (const float*)d_in[18];
    const float* mlp_w2  = (const float*)d_in[19];
    const float* mlp_b2  = (const float*)d_in[20];
    const float* lno_g   = (const float*)d_in[21];
    const float* lno_b   = (const float*)d_in[22];
    const float* head_w  = (const float*)d_in[23];
    const float* head_b  = (const float*)d_in[24];
    float* out = (float*)d_out;

    float *x, *ln, *proj, *u, *dtb, *y, *ff, *te, *wtf, *sP, *sS, *sH0;
    cudaGetSymbolAddress((void**)&x,    g_x);
    cudaGetSymbolAddress((void**)&ln,   g_ln);
    cudaGetSymbolAddress((void**)&proj, g_proj);
    cudaGetSymbolAddress((void**)&u,    g_u);
    cudaGetSymbolAddress((void**)&dtb,  g_dt);
    cudaGetSymbolAddress((void**)&y,    g_y);
    cudaGetSymbolAddress((void**)&ff,   g_ff);
    cudaGetSymbolAddress((void**)&te,   g_te);
    cudaGetSymbolAddress((void**)&wtf,  g_wtf);
    cudaGetSymbolAddress((void**)&sP,   g_scanP);
    cudaGetSymbolAddress((void**)&sS,   g_scanS);
    cudaGetSymbolAddress((void**)&sH0,  g_scanH0);

    // raise dynamic smem limits (host API)
    cudaFuncSetAttribute((const void*)gemm_tc2<128, 128, 0, false, false, false>, cudaFuncAttributeMaxDynamicSharedMemorySize, (2*128*32+2*128*32)*4);
    cudaFuncSetAttribute((const void*)gemm_tc2<64, 128, 2, false, false, true>,   cudaFuncAttributeMaxDynamicSharedMemorySize, (2*64*32+2*128*32)*4);
    cudaFuncSetAttribute((const void*)gemm_tc2<64, 64, 0, false, false, false>,   cudaFuncAttributeMaxDynamicSharedMemorySize, (2*64*32+2*64*32)*4);
    cudaFuncSetAttribute((const void*)gemm_tc2<64, 64, 1, false, true, false>,    cudaFuncAttributeMaxDynamicSharedMemorySize, (2*64*32+2*64*32)*4);
    cudaFuncSetAttribute((const void*)gemm_tc2<64, 64, 0, true, false, false>,    cudaFuncAttributeMaxDynamicSharedMemorySize, (2*64*32+2*64*32)*4);

    float* inw_t  = wtf + OFF_INW;
    float* dtw_t  = wtf + OFF_DTW;
    float* outw_t = wtf + OFF_OUTW;
    float* w1_t   = wtf + OFF_W1;
    float* w2_t   = wtf + OFF_W2;
    float* head_t = wtf + OFF_HEAD;

    // pre-round all GEMM weights to the tf32 grid (once per call)
    {
        int n;
        n = DEPTH * PW * DD / 4;   roundw_kernel<<<(n + 255) / 256, 256>>>((const float4*)in_w,   (float4*)inw_t,  n);
        n = DEPTH * DD * RR / 4;   roundw_kernel<<<(n + 255) / 256, 256>>>((const float4*)dt_w,   (float4*)dtw_t,  n);
        n = DEPTH * DD * DD / 4;   roundw_kernel<<<(n + 255) / 256, 256>>>((const float4*)out_w,  (float4*)outw_t, n);
        n = DEPTH * DFF * DD / 4;  roundw_kernel<<<(n + 255) / 256, 256>>>((const float4*)mlp_w1, (float4*)w1_t,   n);
        n = DEPTH * DD * DFF / 4;  roundw_kernel<<<(n + 255) / 256, 256>>>((const float4*)mlp_w2, (float4*)w2_t,   n);
        n = VOC * DD / 4;          roundw_kernel<<<(n + 255) / 256, 256>>>((const float4*)head_w, (float4*)head_t, n);
    }

    te_kernel<<<BB, 256>>>(t_in, tmlp_w1, tmlp_b1, tmlp_w2, tmlp_b2, te);
    embed_kernel<<<TT * DD / 256, 256>>>(x_t, tok_emb, te, x);

    const int scan_blocks = NCH * BB * DD * NSt / 256;   // 512

    for (int i = 0; i < DEPTH; i++) {
        ln_kernel<<<TT, 256>>>(x, ln1_g + i * DD, ln1_b + i * DD, ln);
        launch_gemm<64, 64, 0, false, false, false>(ln, DD, inw_t + (size_t)i * PW * DD, DD, nullptr,
                                                    proj, PW, TT, PW, DD);
        conv_silu_kernel<<<TT * DD / 256, 256>>>(proj, conv_w + (size_t)i * DD * 4, u);
        launch_gemm<64, 64, 1, false, true, false>(proj + 2 * DD, PW, dtw_t + (size_t)i * DD * RR, RR, dt_b + i * DD,
                                                   dtb, DD, TT, DD, RR);
        scan_p1<<<scan_blocks, 256>>>(proj, dtb, u, sP, sS);
        scan_p2<<<BB * DD * NSt / 256, 256>>>(sP, sS, sH0);
        scan_p3<<<scan_blocks, 256>>>(proj, dtb, u, D_p + i * DD, sH0, y);
        launch_gemm<64, 64, 0, true, false, false>(y, DD, outw_t + (size_t)i * DD * DD, DD, nullptr,
                                                   x, DD, TT, DD, DD);
        ln_kernel<<<TT, 256>>>(x, ln2_g + i * DD, ln2_b + i * DD, ln);
        launch_gemm<64, 128, 2, false, false, true>(ln, DD, w1_t + (size_t)i * DFF * DD, DD, mlp_b1 + i * DFF,
                                                    ff, DFF, TT, DFF, DD);
        launch_gemm<64, 64, 0, true, false, false>(ff, DFF, w2_t + (size_t)i * DD * DFF, DFF, mlp_b2 + i * DD,
                                                   x, DD, TT, DD, DFF);
    }

    ln_kernel<<<TT, 256>>>(x, lno_g, lno_b, ln);
    launch_gemm<128, 128, 0, false, false, false>(ln, DD, head_t, DD, head_b, out, VOC, TT, VOC, DD);
}

// round 5
// speedup vs baseline: 2.9444x; 1.0126x over previous
#include <cuda_runtime.h>
#include <math.h>
#include <stdint.h>

// ---------------- problem constants ----------------
#define TT    2048        // B*L tokens
#define BB    2
#define LL    1024
#define DD    512
#define NSt   16
#define RR    32
#define PW    1088        // 2D + R + 2N
#define DFF   2048
#define VOC   50000
#define DEPTH 6
#define NCH   8           // scan chunks
#define CHL   128         // chunk length

// ---------------- device scratch (no allocs allowed) ----------------
__device__ float g_x   [TT * DD];
__device__ float g_ln  [TT * DD];
__device__ float g_proj[TT * PW];
__device__ float g_u   [TT * DD];
__device__ float g_dt  [TT * DD];
__device__ float g_y   [TT * DD];
__device__ float g_ff  [TT * DFF];
__device__ float g_te  [BB * DD];
__device__ float g_scanP [NCH * BB * DD * NSt];
__device__ float g_scanS [NCH * BB * DD * NSt];
__device__ float g_scanH0[NCH * BB * DD * NSt];

// pre-rounded (TF32-representable) weights
#define OFF_INW  0
#define OFF_DTW  3342336       // + 6*1088*512
#define OFF_OUTW 3440640       // + 6*512*32
#define OFF_W1   5013504       // + 6*512*512
#define OFF_W2   11304960      // + 6*2048*512
#define OFF_HEAD 17596416      // + 6*2048*512
#define WTF_TOTAL 43196416     // + 50000*512
__device__ float g_wtf[WTF_TOTAL];

// ---------------- PTX helpers ----------------
__device__ __forceinline__ void cp_async16(void* dst, const void* src, bool pred) {
    uint32_t d = (uint32_t)__cvta_generic_to_shared(dst);
    int sz = pred ? 16 : 0;
    asm volatile("cp.async.cg.shared.global [%0], [%1], 16, %2;\n" :: "r"(d), "l"(src), "r"(sz));
}
__device__ __forceinline__ void cp_commit() { asm volatile("cp.async.commit_group;\n"); }
template <int NN>
__device__ __forceinline__ void cp_wait() { asm volatile("cp.async.wait_group %0;\n" :: "n"(NN)); }

__device__ __forceinline__ uint32_t f2tf32(float x) {
    uint32_t r;
    asm("cvt.rna.tf32.f32 %0, %1;\n" : "=r"(r) : "f"(x));
    return r;
}
__device__ __forceinline__ float round_tf32(float x) { return __uint_as_float(f2tf32(x)); }

__device__ __forceinline__ void mma_tf32(float c[4],
                                         uint32_t a0, uint32_t a1, uint32_t a2, uint32_t a3,
                                         uint32_t b0, uint32_t b1) {
    asm volatile(
        "mma.sync.aligned.m16n8k8.row.col.f32.tf32.tf32.f32 "
        "{%0,%1,%2,%3}, {%4,%5,%6,%7}, {%8,%9}, {%0,%1,%2,%3};\n"
        : "+f"(c[0]), "+f"(c[1]), "+f"(c[2]), "+f"(c[3])
        : "r"(a0), "r"(a1), "r"(a2), "r"(a3), "r"(b0), "r"(b1));
}

__device__ __forceinline__ void ldsm_x4(uint32_t r[4], uint32_t saddr) {
    asm volatile("ldmatrix.sync.aligned.m8n8.x4.shared.b16 {%0,%1,%2,%3}, [%4];\n"
        : "=r"(r[0]), "=r"(r[1]), "=r"(r[2]), "=r"(r[3]) : "r"(saddr));
}

// ---------------- weight pre-rounding ----------------
__global__ void roundw_kernel(const float4* __restrict__ s, float4* __restrict__ d, int n4) {
    int i = blockIdx.x * 256 + threadIdx.x;
    if (i < n4) {
        float4 v = s[i];
        v.x = round_tf32(v.x); v.y = round_tf32(v.y);
        v.z = round_tf32(v.z); v.w = round_tf32(v.w);
        d[i] = v;
    }
}

// ---------------- time-embedding MLP (tiny) ----------------
__global__ void te_kernel(const int* __restrict__ t_in,
                          const float* __restrict__ w1, const float* __restrict__ b1,
                          const float* __restrict__ w2, const float* __restrict__ b2,
                          float* __restrict__ te)
{
    int b = blockIdx.x;
    int tid = threadIdx.x;            // 256 threads
    __shared__ float s0[DD];
    __shared__ float h1[4 * DD];

    double tv = (double)t_in[b];
    {
        double f = exp((double)tid * (-9.210340371976184 / 255.0));
        double e = tv * f;
        s0[tid]       = (float)sin(e);
        s0[tid + 256] = (float)cos(e);
    }
    __syncthreads();

    for (int j = tid; j < 4 * DD; j += 256) {
        const float* wr = w1 + (size_t)j * DD;
        float acc = b1[j];
        #pragma unroll 8
        for (int k = 0; k < DD; k++) acc = fmaf(s0[k], wr[k], acc);
        h1[j] = acc / (1.0f + expf(-acc));
    }
    __syncthreads();

    for (int j = tid; j < DD; j += 256) {
        const float* wr = w2 + (size_t)j * (4 * DD);
        float acc = b2[j];
        #pragma unroll 8
        for (int k = 0; k < 4 * DD; k++) acc = fmaf(h1[k], wr[k], acc);
        te[b * DD + j] = acc;
    }
}

// ---------------- embedding gather + te add ----------------
__global__ void embed_kernel(const int* __restrict__ x_t,
                             const float* __restrict__ tok_emb,
                             const float* __restrict__ te,
                             float* __restrict__ x)
{
    int idx = blockIdx.x * 256 + threadIdx.x;
    int d = idx & (DD - 1);
    int t = idx >> 9;
    int b = t >> 10;
    int tok = x_t[t];
    x[idx] = tok_emb[(size_t)tok * DD + d] + te[b * DD + d];
}

// ---------------- LayerNorm (two-pass, per token); output rounded to tf32 ----------------
__global__ __launch_bounds__(256) void ln_kernel(const float* __restrict__ x,
                                                 const float* __restrict__ g,
                                                 const float* __restrict__ bta,
                                                 float* __restrict__ o)
{
    int t = blockIdx.x;
    int tid = threadIdx.x;
    const float* row = x + (size_t)t * DD;
    float v0 = row[tid], v1 = row[tid + 256];

    __shared__ float red[8];
    __shared__ float mean_s, rstd_s;

    float s = v0 + v1;
    #pragma unroll
    for (int off = 16; off > 0; off >>= 1) s += __shfl_xor_sync(0xffffffffu, s, off);
    if ((tid & 31) == 0) red[tid >> 5] = s;
    __syncthreads();
    if (tid == 0) {
        float tot = 0.f;
        #pragma unroll
        for (int i = 0; i < 8; i++) tot += red[i];
        mean_s = tot * (1.0f / DD);
    }
    __syncthreads();
    float mu = mean_s;
    float d0 = v0 - mu, d1 = v1 - mu;
    float q = d0 * d0 + d1 * d1;
    #pragma unroll
    for (int off = 16; off > 0; off >>= 1) q += __shfl_xor_sync(0xffffffffu, q, off);
    if ((tid & 31) == 0) red[tid >> 5] = q;
    __syncthreads();
    if (tid == 0) {
        float tot = 0.f;
        #pragma unroll
        for (int i = 0; i < 8; i++) tot += red[i];
        rstd_s = rsqrtf(tot * (1.0f / DD) + 1e-5f);
    }
    __syncthreads();
    float rs = rstd_s;
    o[(size_t)t * DD + tid]       = round_tf32(d0 * rs * g[tid]       + bta[tid]);
    o[(size_t)t * DD + tid + 256] = round_tf32(d1 * rs * g[tid + 256] + bta[tid + 256]);
}

// ---------------- TF32 tensor-core GEMM v4 ----------------
// C[M,N] = A[M,K] @ W[N,K]^T. brow = blockIdx.x (M fast -> consecutive CTAs
// share the W tile; W streamed from HBM once). ldmatrix.x4 fragment loads +
// 2-deep register fragment pipeline. BK=32, 128 threads = 4 warps (2x2),
// warp tile (BM/2) x (BN/2). M % BM == 0 assumed. Weights pre-rounded.
template <int BM, int BN, int EPI, bool ACC, bool CVT_A, bool ROUND_OUT>
__global__ __launch_bounds__(128) void gemm_tc4(
    const float* __restrict__ A, int lda,
    const float* __restrict__ W, int ldw,
    const float* __restrict__ bias,
    float* __restrict__ C, int ldc,
    int M, int N, int K)
{
    constexpr int MT = BM / 32;            // m16 tiles per warp
    constexpr int NT = BN / 16;            // n8 tiles per warp
    constexpr int NP = NT / 2;             // ldmatrix.x4 B loads per s-step
    constexpr int ABUF = BM * 32;          // floats per A k-tile buffer
    constexpr int BBUF = BN * 32;

    extern __shared__ float sm[];
    const uint32_t smem_u32 = (uint32_t)__cvta_generic_to_shared(sm);

    const int tid  = threadIdx.x;
    const int lane = tid & 31;
    const int wid  = tid >> 5;
    const int wm   = (wid & 1) * (BM / 2);
    const int wn   = (wid >> 1) * (BN / 2);
    const int brow = blockIdx.x * BM;      // M fast
    const int bcol = blockIdx.y * BN;
    const int lq   = lane >> 2;
    const int lr   = lane & 3;

    // per-thread ldmatrix row addressing (byte offsets within a k-tile buffer)
    const int hiA = lane >> 4;             // chunk +0/+1 selector for A
    const int hiB = (lane >> 3) & 1;       // chunk +0/+1 selector for B
    uint32_t baseA[MT]; int rA7[MT];
    #pragma unroll
    for (int mt = 0; mt < MT; mt++) {
        int r = wm + mt * 16 + (lane & 15);
        baseA[mt] = (uint32_t)r * 128;     // r*32 floats * 4B
        rA7[mt] = r & 7;
    }
    uint32_t baseB[NP]; int rB7[NP];
    #pragma unroll
    for (int p = 0; p < NP; p++) {
        int r = wn + p * 16 + (lane & 7) + ((lane >> 4) << 3);
        baseB[p] = (uint32_t)r * 128;
        rB7[p] = r & 7;
    }

    float acc[MT][NT][4];
    #pragma unroll
    for (int i = 0; i < MT; i++)
        #pragma unroll
        for (int j = 0; j < NT; j++)
            #pragma unroll
            for (int v = 0; v < 4; v++) acc[i][j][v] = 0.f;

    const int KT = K >> 5;

    auto load_tile = [&](int buf, int k0) {
        float* Abuf = sm + buf * ABUF;
        float* Bbuf = sm + 2 * ABUF + buf * BBUF;
        if (BM == 128) {
            int m = tid;
            const float* src = A + (size_t)(brow + m) * lda + k0;
            float* drow = Abuf + m * 32;
            #pragma unroll
            for (int c = 0; c < 8; c++)
                cp_async16(drow + ((c ^ (m & 7)) << 2), src + c * 4, true);
        } else {
            int m = tid >> 1;
            int cb = (tid & 1) * 4;
            const float* src = A + (size_t)(brow + m) * lda + k0;
            float* drow = Abuf + m * 32;
            #pragma unroll
            for (int c = 0; c < 4; c++)
                cp_async16(drow + (((cb + c) ^ (m & 7)) << 2), src + (cb + c) * 4, true);
        }
        if (BN == 128) {
            int n = tid;
            const float* src = W + (size_t)(bcol + n) * ldw + k0;
            bool pv = (bcol + n) < N;
            float* drow = Bbuf + n * 32;
            #pragma unroll
            for (int c = 0; c < 8; c++)
                cp_async16(drow + ((c ^ (n & 7)) << 2), src + c * 4, pv);
        } else if (BN == 64) {
            int n = tid >> 1;
            int cb = (tid & 1) * 4;
            const float* src = W + (size_t)(bcol + n) * ldw + k0;
            bool pv = (bcol + n) < N;
            float* drow = Bbuf + n * 32;
            #pragma unroll
            for (int c = 0; c < 4; c++)
                cp_async16(drow + (((cb + c) ^ (n & 7)) << 2), src + (cb + c) * 4, pv);
        } else {  // BN == 32
            int n = tid >> 2;
            int cb = (tid & 3) * 2;
            const float* src = W + (size_t)(bcol + n) * ldw + k0;
            bool pv = (bcol + n) < N;
            float* drow = Bbuf + n * 32;
            #pragma unroll
            for (int c = 0; c < 2; c++)
                cp_async16(drow + (((cb + c) ^ (n & 7)) << 2), src + (cb + c) * 4, pv);
        }
    };

    load_tile(0, 0);
    cp_commit();

    uint32_t af[2][MT][4], bf[2][NP][4];

    for (int kt = 0; kt < KT; kt++) {
        if (kt + 1 < KT) {
            load_tile((kt + 1) & 1, (kt + 1) * 32);
            cp_commit();
            cp_wait<1>();
        } else {
            cp_wait<0>();
        }
        __syncthreads();

        const uint32_t aBase = smem_u32 + (uint32_t)((kt & 1) * ABUF) * 4;
        const uint32_t bBase = smem_u32 + (uint32_t)(2 * ABUF + (kt & 1) * BBUF) * 4;

        auto ldfrags = [&](int sb, int s) {
            #pragma unroll
            for (int mt = 0; mt < MT; mt++) {
                ldsm_x4(af[sb][mt], aBase + baseA[mt] + (uint32_t)(((2 * s + hiA) ^ rA7[mt]) << 4));
                if (CVT_A) {
                    #pragma unroll
                    for (int v = 0; v < 4; v++)
                        af[sb][mt][v] = f2tf32(__uint_as_float(af[sb][mt][v]));
                }
            }
            #pragma unroll
            for (int p = 0; p < NP; p++)
                ldsm_x4(bf[sb][p], bBase + baseB[p] + (uint32_t)(((2 * s + hiB) ^ rB7[p]) << 4));
        };

        ldfrags(0, 0);
        #pragma unroll
        for (int s = 0; s < 4; s++) {
            if (s < 3) ldfrags((s + 1) & 1, s + 1);
            const int sb = s & 1;
            #pragma unroll
            for (int mt = 0; mt < MT; mt++)
                #pragma unroll
                for (int nt = 0; nt < NT; nt++) {
                    const int p = nt >> 1, o = (nt & 1) * 2;
                    mma_tf32(acc[mt][nt],
                             af[sb][mt][0], af[sb][mt][1], af[sb][mt][2], af[sb][mt][3],
                             bf[sb][p][o], bf[sb][p][o + 1]);
                }
        }
        __syncthreads();
    }

    // ---- epilogue ----
    #pragma unroll
    for (int mt = 0; mt < MT; mt++) {
        int r0 = brow + wm + mt * 16 + lq;
        int r1 = r0 + 8;
        #pragma unroll
        for (int nt = 0; nt < NT; nt++) {
            int c = bcol + wn + nt * 8 + lr * 2;
            if (c >= N) continue;
            float v0 = acc[mt][nt][0], v1 = acc[mt][nt][1];
            float v2 = acc[mt][nt][2], v3 = acc[mt][nt][3];
            if (bias) {
                float b0 = __ldg(bias + c), b1 = __ldg(bias + c + 1);
                v0 += b0; v1 += b1; v2 += b0; v3 += b1;
            }
            if (EPI == 1) {
                v0 = (v0 > 20.f) ? v0 : log1pf(expf(v0));
                v1 = (v1 > 20.f) ? v1 : log1pf(expf(v1));
                v2 = (v2 > 20.f) ? v2 : log1pf(expf(v2));
                v3 = (v3 > 20.f) ? v3 : log1pf(expf(v3));
            }
            if (EPI == 2) {
                const float is2 = 0.70710678118654752f;
                v0 = 0.5f * v0 * (1.f + erff(v0 * is2));
                v1 = 0.5f * v1 * (1.f + erff(v1 * is2));
                v2 = 0.5f * v2 * (1.f + erff(v2 * is2));
                v3 = 0.5f * v3 * (1.f + erff(v3 * is2));
            }
            float* p0 = C + (size_t)r0 * ldc + c;
            float* p1 = C + (size_t)r1 * ldc + c;
            if (ACC) {
                float2 o0 = *(float2*)p0, o1 = *(float2*)p1;
                v0 += o0.x; v1 += o0.y; v2 += o1.x; v3 += o1.y;
            }
            if (ROUND_OUT) {
                v0 = round_tf32(v0); v1 = round_tf32(v1);
                v2 = round_tf32(v2); v3 = round_tf32(v3);
            }
            *(float2*)p0 = make_float2(v0, v1);
            *(float2*)p1 = make_float2(v2, v3);
        }
    }
}

// ---------------- depthwise causal conv (DCONV=4) + silu ----------------
__global__ void conv_silu_kernel(const float* __restrict__ proj,
                                 const float* __restrict__ w,
                                 float* __restrict__ u)
{
    int idx = blockIdx.x * 256 + threadIdx.x;
    int d = idx & (DD - 1);
    int t = idx >> 9;
    int l = t & (LL - 1);
    const float* wd = w + d * 4;
    float acc = 0.f;
    #pragma unroll
    for (int k = 0; k < 4; k++) {
        int ll = l - 3 + k;
        if (ll >= 0) acc = fmaf(proj[(size_t)(t - 3 + k) * PW + d], wd[k], acc);
    }
    u[idx] = acc / (1.0f + expf(-acc));
}

// ---------------- chunked selective-scan ----------------
__global__ __launch_bounds__(256) void scan_p1(const float* __restrict__ proj,
                                               const float* __restrict__ dt,
                                               const float* __restrict__ u,
                                               float* __restrict__ P,
                                               float* __restrict__ S)
{
    int idx = blockIdx.x * 256 + threadIdx.x;     // over NCH*BB*DD*NSt
    int n  = idx & 15;
    int hw = idx >> 4;
    int c  = hw >> 10;
    int b  = (hw >> 9) & 1;
    int d  = hw & 511;

    const float coef = -(float)(n + 1);
    const float inv  = -1.0f / (float)(n + 1);
    int t0 = b * LL + c * CHL;

    const float* dtP = dt + (size_t)t0 * DD + d;
    const float* uP  = u  + (size_t)t0 * DD + d;
    const float* BP  = proj + (size_t)t0 * PW + 2 * DD + RR + n;

    float Pr = 1.f, h = 0.f;
    float dtv = dtP[0], uv = uP[0], Bn = BP[0];
    for (int l = 0; l < CHL; l++) {
        float dt2 = 0.f, u2 = 0.f, B2 = 0.f;
        if (l + 1 < CHL) {
            dt2 = dtP[(size_t)(l + 1) * DD];
            u2  = uP [(size_t)(l + 1) * DD];
            B2  = BP [(size_t)(l + 1) * PW];
        }
        float a = __expf(dtv * coef);
        Pr *= a;
        h = fmaf(a, h, (a - 1.f) * inv * Bn * uv);
        dtv = dt2; uv = u2; Bn = B2;
    }
    P[idx] = Pr;
    S[idx] = h;
}

__global__ __launch_bounds__(256) void scan_p2(const float* __restrict__ P,
                                               const float* __restrict__ S,
                                               float* __restrict__ h0)
{
    int idx = blockIdx.x * 256 + threadIdx.x;     // over BB*DD*NSt
    float H = 0.f;
    #pragma unroll
    for (int c = 0; c < NCH; c++) {
        int off = c * (BB * DD * NSt) + idx;
        h0[off] = H;
        H = fmaf(P[off], H, S[off]);
    }
}

__global__ __launch_bounds__(256) void scan_p3(const float* __restrict__ proj,
                                               const float* __restrict__ dt,
                                               const float* __restrict__ u,
                                               const float* __restrict__ Dp,
                                               const float* __restrict__ h0,
                                               float* __restrict__ y)
{
    int idx = blockIdx.x * 256 + threadIdx.x;
    int n  = idx & 15;
    int hw = idx >> 4;
    int c  = hw >> 10;
    int b  = (hw >> 9) & 1;
    int d  = hw & 511;

    const float coef = -(float)(n + 1);
    const float inv  = -1.0f / (float)(n + 1);
    const float dval = Dp[d];
    int t0 = b * LL + c * CHL;

    const float* dtP = dt + (size_t)t0 * DD + d;
    const float* uP  = u  + (size_t)t0 * DD + d;
    const float* rowP = proj + (size_t)t0 * PW;
    float*       yP  = y  + (size_t)t0 * DD + d;

    float h = h0[idx];
    float dtv = dtP[0];
    float uv  = uP[0];
    float zv  = rowP[DD + d];
    float Bn  = rowP[2 * DD + RR + n];
    float Cn  = rowP[2 * DD + RR + NSt + n];

    for (int l = 0; l < CHL; l++) {
        float dt2 = 0.f, u2 = 0.f, z2 = 0.f, B2 = 0.f, C2 = 0.f;
        if (l + 1 < CHL) {
            dt2 = dtP[(size_t)(l + 1) * DD];
            u2  = uP [(size_t)(l + 1) * DD];
            const float* row = rowP + (size_t)(l + 1) * PW;
            z2 = row[DD + d];
            B2 = row[2 * DD + RR + n];
            C2 = row[2 * DD + RR + NSt + n];
        }
        float a  = __expf(dtv * coef);
        h = fmaf(a, h, (a - 1.f) * inv * Bn * uv);
        float p = Cn * h;
        p += __shfl_xor_sync(0xffffffffu, p, 8);
        p += __shfl_xor_sync(0xffffffffu, p, 4);
        p += __shfl_xor_sync(0xffffffffu, p, 2);
        p += __shfl_xor_sync(0xffffffffu, p, 1);
        if (n == 0) {
            float sz = zv / (1.f + __expf(-zv));
            yP[(size_t)l * DD] = round_tf32((p + uv * dval) * sz);
        }
        dtv = dt2; uv = u2; zv = z2; Bn = B2; Cn = C2;
    }
}

// ---------------- host-side GEMM dispatch ----------------
template <int BM, int BN, int EPI, bool ACC, bool CVT_A, bool RO>
static inline void launch_gemm(const float* A, int lda, const float* W, int ldw,
                               const float* bias, float* C, int ldc,
                               int M, int N, int K)
{
    dim3 grid(M / BM, (N + BN - 1) / BN);   // M fast
    size_t smem = (size_t)(2 * BM * 32 + 2 * BN * 32) * 4;
    gemm_tc4<BM, BN, EPI, ACC, CVT_A, RO><<<grid, 128, smem>>>(A, lda, W, ldw, bias, C, ldc, M, N, K);
}

// ---------------- entry point ----------------
extern "C" void kernel_launch(void* const* d_in, const int* in_sizes, int n_in,
                              void* d_out, int out_size)
{
    const int*   x_t     = (const int*)  d_in[0];
    const int*   t_in    = (const int*)  d_in[1];
    const float* tok_emb = (const float*)d_in[2];
    const float* tmlp_w1 = (const float*)d_in[3];
    const float* tmlp_b1 = (const float*)d_in[4];
    const float* tmlp_w2 = (const float*)d_in[5];
    const float* tmlp_b2 = (const float*)d_in[6];
    const float* ln1_g   = (const float*)d_in[7];
    const float* ln1_b   = (const float*)d_in[8];
    const float* in_w    = (const float*)d_in[9];
    const float* conv_w  = (const float*)d_in[10];
    const float* dt_w    = (const float*)d_in[11];
    const float* dt_b    = (const float*)d_in[12];
    const float* D_p     = (const float*)d_in[13];
    const float* out_w   = (const float*)d_in[14];
    const float* ln2_g   = (const float*)d_in[15];
    const float* ln2_b   = (const float*)d_in[16];
    const float* mlp_w1  = (const float*)d_in[17];
    const float* mlp_b1  = (const float*)d_in[18];
    const float* mlp_w2  = (const float*)d_in[19];
    const float* mlp_b2  = (const float*)d_in[20];
    const float* lno_g   = (const float*)d_in[21];
    const float* lno_b   = (const float*)d_in[22];
    const float* head_w  = (const float*)d_in[23];
    const float* head_b  = (const float*)d_in[24];
    float* out = (float*)d_out;

    float *x, *ln, *proj, *u, *dtb, *y, *ff, *te, *wtf, *sP, *sS, *sH0;
    cudaGetSymbolAddress((void**)&x,    g_x);
    cudaGetSymbolAddress((void**)&ln,   g_ln);
    cudaGetSymbolAddress((void**)&proj, g_proj);
    cudaGetSymbolAddress((void**)&u,    g_u);
    cudaGetSymbolAddress((void**)&dtb,  g_dt);
    cudaGetSymbolAddress((void**)&y,    g_y);
    cudaGetSymbolAddress((void**)&ff,   g_ff);
    cudaGetSymbolAddress((void**)&te,   g_te);
    cudaGetSymbolAddress((void**)&wtf,  g_wtf);
    cudaGetSymbolAddress((void**)&sP,   g_scanP);
    cudaGetSymbolAddress((void**)&sS,   g_scanS);
    cudaGetSymbolAddress((void**)&sH0,  g_scanH0);

    // raise dynamic smem limits (host API)
    cudaFuncSetAttribute((const void*)gemm_tc4<64, 64, 0, false, false, false>,  cudaFuncAttributeMaxDynamicSharedMemorySize, (2*64*32+2*64*32)*4);
    cudaFuncSetAttribute((const void*)gemm_tc4<64, 32, 1, false, true, false>,   cudaFuncAttributeMaxDynamicSharedMemorySize, (2*64*32+2*32*32)*4);
    cudaFuncSetAttribute((const void*)gemm_tc4<64, 32, 0, true, false, false>,   cudaFuncAttributeMaxDynamicSharedMemorySize, (2*64*32+2*32*32)*4);
    cudaFuncSetAttribute((const void*)gemm_tc4<64, 128, 2, false, false, true>,  cudaFuncAttributeMaxDynamicSharedMemorySize, (2*64*32+2*128*32)*4);
    cudaFuncSetAttribute((const void*)gemm_tc4<64, 128, 0, false, false, false>, cudaFuncAttributeMaxDynamicSharedMemorySize, (2*64*32+2*128*32)*4);

    float* inw_t  = wtf + OFF_INW;
    float* dtw_t  = wtf + OFF_DTW;
    float* outw_t = wtf + OFF_OUTW;
    float* w1_t   = wtf + OFF_W1;
    float* w2_t   = wtf + OFF_W2;
    float* head_t = wtf + OFF_HEAD;

    // pre-round all GEMM weights to the tf32 grid (once per call)
    {
        int n;
        n = DEPTH * PW * DD / 4;   roundw_kernel<<<(n + 255) / 256, 256>>>((const float4*)in_w,   (float4*)inw_t,  n);
        n = DEPTH * DD * RR / 4;   roundw_kernel<<<(n + 255) / 256, 256>>>((const float4*)dt_w,   (float4*)dtw_t,  n);
        n = DEPTH * DD * DD / 4;   roundw_kernel<<<(n + 255) / 256, 256>>>((const float4*)out_w,  (float4*)outw_t, n);
        n = DEPTH * DFF * DD / 4;  roundw_kernel<<<(n + 255) / 256, 256>>>((const float4*)mlp_w1, (float4*)w1_t,   n);
        n = DEPTH * DD * DFF / 4;  roundw_kernel<<<(n + 255) / 256, 256>>>((const float4*)mlp_w2, (float4*)w2_t,   n);
        n = VOC * DD / 4;          roundw_kernel<<<(n + 255) / 256, 256>>>((const float4*)head_w, (float4*)head_t, n);
    }

    te_kernel<<<BB, 256>>>(t_in, tmlp_w1, tmlp_b1, tmlp_w2, tmlp_b2, te);
    embed_kernel<<<TT * DD / 256, 256>>>(x_t, tok_emb, te, x);

    const int scan_blocks = NCH * BB * DD * NSt / 256;   // 512

    for (int i = 0; i < DEPTH; i++) {
        ln_kernel<<<TT, 256>>>(x, ln1_g + i * DD, ln1_b + i * DD, ln);
        launch_gemm<64, 64, 0, false, false, false>(ln, DD, inw_t + (size_t)i * PW * DD, DD, nullptr,
                                                    proj, PW, TT, PW, DD);
        conv_silu_kernel<<<TT * DD / 256, 256>>>(proj, conv_w + (size_t)i * DD * 4, u);
        launch_gemm<64, 32, 1, false, true, false>(proj + 2 * DD, PW, dtw_t + (size_t)i * DD * RR, RR, dt_b + i * DD,
                                                   dtb, DD, TT, DD, RR);
        scan_p1<<<scan_blocks, 256>>>(proj, dtb, u, sP, sS);
        scan_p2<<<BB * DD * NSt / 256, 256>>>(sP, sS, sH0);
        scan_p3<<<scan_blocks, 256>>>(proj, dtb, u, D_p + i * DD, sH0, y);
        launch_gemm<64, 32, 0, true, false, false>(y, DD, outw_t + (size_t)i * DD * DD, DD, nullptr,
                                                   x, DD, TT, DD, DD);
        ln_kernel<<<TT, 256>>>(x, ln2_g + i * DD, ln2_b + i * DD, ln);
        launch_gemm<64, 128, 2, false, false, true>(ln, DD, w1_t + (size_t)i * DFF * DD, DD, mlp_b1 + i * DFF,
                                                    ff, DFF, TT, DFF, DD);
        launch_gemm<64, 32, 0, true, false, false>(ff, DFF, w2_t + (size_t)i * DD * DFF, DFF, mlp_b2 + i * DD,
                                                   x, DD, TT, DD, DFF);
    }

    ln_kernel<<<TT, 256>>>(x, lno_g, lno_b, ln);
    launch_gemm<64, 128, 0, false, false, false>(ln, DD, head_t, DD, head_b, out, VOC, TT, VOC, DD);
}

// round 7
// speedup vs baseline: 3.0770x; 1.0451x over previous
#include <cuda_runtime.h>
#include <math.h>
#include <stdint.h>

// ---------------- problem constants ----------------
#define TT    2048        // B*L tokens
#define BB    2
#define LL    1024
#define DD    512
#define NSt   16
#define RR    32
#define PW    1088        // 2D + R + 2N
#define DFF   2048
#define VOC   50000
#define DEPTH 6
#define NCH   32          // scan chunks
#define CHL   32          // chunk length

// ---------------- device scratch (no allocs allowed) ----------------
__device__ float g_x   [TT * DD];
__device__ float g_ln  [TT * DD];
__device__ float g_proj[TT * PW];
__device__ float g_u   [TT * DD];
__device__ float g_dt  [TT * DD];
__device__ float g_y   [TT * DD];
__device__ float g_ff  [TT * DFF];
__device__ float g_te  [BB * DD];
__device__ float g_scanP [NCH * BB * DD * NSt];
__device__ float g_scanS [NCH * BB * DD * NSt];
__device__ float g_scanH0[NCH * BB * DD * NSt];

// pre-rounded (TF32-representable) weights
#define OFF_INW  0
#define OFF_DTW  3342336       // + 6*1088*512
#define OFF_OUTW 3440640       // + 6*512*32
#define OFF_W1   5013504       // + 6*512*512
#define OFF_W2   11304960      // + 6*2048*512
#define OFF_HEAD 17596416      // + 6*2048*512
#define WTF_TOTAL 43196416     // + 50000*512
__device__ float g_wtf[WTF_TOTAL];

// ---------------- PTX helpers ----------------
__device__ __forceinline__ void cp_async16(void* dst, const void* src, bool pred) {
    uint32_t d = (uint32_t)__cvta_generic_to_shared(dst);
    int sz = pred ? 16 : 0;
    asm volatile("cp.async.cg.shared.global [%0], [%1], 16, %2;\n" :: "r"(d), "l"(src), "r"(sz));
}
__device__ __forceinline__ void cp_commit() { asm volatile("cp.async.commit_group;\n"); }
template <int NN>
__device__ __forceinline__ void cp_wait() { asm volatile("cp.async.wait_group %0;\n" :: "n"(NN)); }

__device__ __forceinline__ uint32_t f2tf32(float x) {
    uint32_t r;
    asm("cvt.rna.tf32.f32 %0, %1;\n" : "=r"(r) : "f"(x));
    return r;
}
__device__ __forceinline__ float round_tf32(float x) { return __uint_as_float(f2tf32(x)); }

__device__ __forceinline__ void mma_tf32(float c[4],
                                         uint32_t a0, uint32_t a1, uint32_t a2, uint32_t a3,
                                         uint32_t b0, uint32_t b1) {
    asm volatile(
        "mma.sync.aligned.m16n8k8.row.col.f32.tf32.tf32.f32 "
        "{%0,%1,%2,%3}, {%4,%5,%6,%7}, {%8,%9}, {%0,%1,%2,%3};\n"
        : "+f"(c[0]), "+f"(c[1]), "+f"(c[2]), "+f"(c[3])
        : "r"(a0), "r"(a1), "r"(a2), "r"(a3), "r"(b0), "r"(b1));
}

__device__ __forceinline__ void ldsm_x4(uint32_t r[4], uint32_t saddr) {
    asm volatile("ldmatrix.sync.aligned.m8n8.x4.shared.b16 {%0,%1,%2,%3}, [%4];\n"
        : "=r"(r[0]), "=r"(r[1]), "=r"(r[2]), "=r"(r[3]) : "r"(saddr));
}

// ---------------- weight pre-rounding ----------------
__global__ void roundw_kernel(const float4* __restrict__ s, float4* __restrict__ d, int n4) {
    int i = blockIdx.x * 256 + threadIdx.x;
    if (i < n4) {
        float4 v = s[i];
        v.x = round_tf32(v.x); v.y = round_tf32(v.y);
        v.z = round_tf32(v.z); v.w = round_tf32(v.w);
        d[i] = v;
    }
}

// ---------------- time-embedding MLP (tiny) ----------------
__global__ void te_kernel(const int* __restrict__ t_in,
                          const float* __restrict__ w1, const float* __restrict__ b1,
                          const float* __restrict__ w2, const float* __restrict__ b2,
                          float* __restrict__ te)
{
    int b = blockIdx.x;
    int tid = threadIdx.x;            // 256 threads
    __shared__ float s0[DD];
    __shared__ float h1[4 * DD];

    double tv = (double)t_in[b];
    {
        double f = exp((double)tid * (-9.210340371976184 / 255.0));
        double e = tv * f;
        s0[tid]       = (float)sin(e);
        s0[tid + 256] = (float)cos(e);
    }
    __syncthreads();

    for (int j = tid; j < 4 * DD; j += 256) {
        const float* wr = w1 + (size_t)j * DD;
        float acc = b1[j];
        #pragma unroll 8
        for (int k = 0; k < DD; k++) acc = fmaf(s0[k], wr[k], acc);
        h1[j] = acc / (1.0f + expf(-acc));
    }
    __syncthreads();

    for (int j = tid; j < DD; j += 256) {
        const float* wr = w2 + (size_t)j * (4 * DD);
        float acc = b2[j];
        #pragma unroll 8
        for (int k = 0; k < 4 * DD; k++) acc = fmaf(h1[k], wr[k], acc);
        te[b * DD + j] = acc;
    }
}

// ---------------- embedding gather + te add ----------------
__global__ void embed_kernel(const int* __restrict__ x_t,
                             const float* __restrict__ tok_emb,
                             const float* __restrict__ te,
                             float* __restrict__ x)
{
    int idx = blockIdx.x * 256 + threadIdx.x;
    int d = idx & (DD - 1);
    int t = idx >> 9;
    int b = t >> 10;
    int tok = x_t[t];
    x[idx] = tok_emb[(size_t)tok * DD + d] + te[b * DD + d];
}

// ---------------- LayerNorm (two-pass, per token); output rounded to tf32 ----------------
__global__ __launch_bounds__(256) void ln_kernel(const float* __restrict__ x,
                                                 const float* __restrict__ g,
                                                 const float* __restrict__ bta,
                                                 float* __restrict__ o)
{
    int t = blockIdx.x;
    int tid = threadIdx.x;
    const float* row = x + (size_t)t * DD;
    float v0 = row[tid], v1 = row[tid + 256];

    __shared__ float red[8];
    __shared__ float mean_s, rstd_s;

    float s = v0 + v1;
    #pragma unroll
    for (int off = 16; off > 0; off >>= 1) s += __shfl_xor_sync(0xffffffffu, s, off);
    if ((tid & 31) == 0) red[tid >> 5] = s;
    __syncthreads();
    if (tid == 0) {
        float tot = 0.f;
        #pragma unroll
        for (int i = 0; i < 8; i++) tot += red[i];
        mean_s = tot * (1.0f / DD);
    }
    __syncthreads();
    float mu = mean_s;
    float d0 = v0 - mu, d1 = v1 - mu;
    float q = d0 * d0 + d1 * d1;
    #pragma unroll
    for (int off = 16; off > 0; off >>= 1) q += __shfl_xor_sync(0xffffffffu, q, off);
    if ((tid & 31) == 0) red[tid >> 5] = q;
    __syncthreads();
    if (tid == 0) {
        float tot = 0.f;
        #pragma unroll
        for (int i = 0; i < 8; i++) tot += red[i];
        rstd_s = rsqrtf(tot * (1.0f / DD) + 1e-5f);
    }
    __syncthreads();
    float rs = rstd_s;
    o[(size_t)t * DD + tid]       = round_tf32(d0 * rs * g[tid]       + bta[tid]);
    o[(size_t)t * DD + tid + 256] = round_tf32(d1 * rs * g[tid + 256] + bta[tid + 256]);
}

// ---------------- TF32 tensor-core GEMM v4 (legacy mma path) ----------------
template <int BM, int BN, int EPI, bool ACC, bool CVT_A, bool ROUND_OUT>
__global__ __launch_bounds__(128) void gemm_tc4(
    const float* __restrict__ A, int lda,
    const float* __restrict__ W, int ldw,
    const float* __restrict__ bias,
    float* __restrict__ C, int ldc,
    int M, int N, int K)
{
    constexpr int MT = BM / 32;
    constexpr int NT = BN / 16;
    constexpr int NP = NT / 2;
    constexpr int ABUF = BM * 32;
    constexpr int BBUF = BN * 32;

    extern __shared__ float sm[];
    const uint32_t smem_u = (uint32_t)__cvta_generic_to_shared(sm);

    const int tid  = threadIdx.x;
    const int lane = tid & 31;
    const int wid  = tid >> 5;
    const int wm   = (wid & 1) * (BM / 2);
    const int wn   = (wid >> 1) * (BN / 2);
    const int brow = blockIdx.x * BM;
    const int bcol = blockIdx.y * BN;
    const int lq   = lane >> 2;
    const int lr   = lane & 3;

    const int hiA = lane >> 4;
    const int hiB = (lane >> 3) & 1;
    uint32_t baseA[MT]; int rA7[MT];
    #pragma unroll
    for (int mt = 0; mt < MT; mt++) {
        int r = wm + mt * 16 + (lane & 15);
        baseA[mt] = (uint32_t)r * 128;
        rA7[mt] = r & 7;
    }
    uint32_t baseB[NP]; int rB7[NP];
    #pragma unroll
    for (int p = 0; p < NP; p++) {
        int r = wn + p * 16 + (lane & 7) + ((lane >> 4) << 3);
        baseB[p] = (uint32_t)r * 128;
        rB7[p] = r & 7;
    }

    float acc[MT][NT][4];
    #pragma unroll
    for (int i = 0; i < MT; i++)
        #pragma unroll
        for (int j = 0; j < NT; j++)
            #pragma unroll
            for (int v = 0; v < 4; v++) acc[i][j][v] = 0.f;

    const int KT = K >> 5;

    auto load_tile = [&](int buf, int k0) {
        float* Abuf = sm + buf * ABUF;
        float* Bbuf = sm + 2 * ABUF + buf * BBUF;
        if (BM == 128) {
            int m = tid;
            const float* src = A + (size_t)(brow + m) * lda + k0;
            float* drow = Abuf + m * 32;
            #pragma unroll
            for (int c = 0; c < 8; c++)
                cp_async16(drow + ((c ^ (m & 7)) << 2), src + c * 4, true);
        } else {
            int m = tid >> 1;
            int cb = (tid & 1) * 4;
            const float* src = A + (size_t)(brow + m) * lda + k0;
            float* drow = Abuf + m * 32;
            #pragma unroll
            for (int c = 0; c < 4; c++)
                cp_async16(drow + (((cb + c) ^ (m & 7)) << 2), src + (cb + c) * 4, true);
        }
        if (BN == 128) {
            int n = tid;
            const float* src = W + (size_t)(bcol + n) * ldw + k0;
            bool pv = (bcol + n) < N;
            float* drow = Bbuf + n * 32;
            #pragma unroll
            for (int c = 0; c < 8; c++)
                cp_async16(drow + ((c ^ (n & 7)) << 2), src + c * 4, pv);
        } else if (BN == 64) {
            int n = tid >> 1;
            int cb = (tid & 1) * 4;
            const float* src = W + (size_t)(bcol + n) * ldw + k0;
            bool pv = (bcol + n) < N;
            float* drow = Bbuf + n * 32;
            #pragma unroll
            for (int c = 0; c < 4; c++)
                cp_async16(drow + (((cb + c) ^ (n & 7)) << 2), src + (cb + c) * 4, pv);
        } else {  // BN == 32
            int n = tid >> 2;
            int cb = (tid & 3) * 2;
            const float* src = W + (size_t)(bcol + n) * ldw + k0;
            bool pv = (bcol + n) < N;
            float* drow = Bbuf + n * 32;
            #pragma unroll
            for (int c = 0; c < 2; c++)
                cp_async16(drow + (((cb + c) ^ (n & 7)) << 2), src + (cb + c) * 4, pv);
        }
    };

    load_tile(0, 0);
    cp_commit();

    uint32_t af[2][MT][4], bf[2][NP][4];

    for (int kt = 0; kt < KT; kt++) {
        if (kt + 1 < KT) {
            load_tile((kt + 1) & 1, (kt + 1) * 32);
            cp_commit();
            cp_wait<1>();
        } else {
            cp_wait<0>();
        }
        __syncthreads();

        const uint32_t aBase = smem_u + (uint32_t)((kt & 1) * ABUF) * 4;
        const uint32_t bBase = smem_u + (uint32_t)(2 * ABUF + (kt & 1) * BBUF) * 4;

        auto ldfrags = [&](int sb, int s) {
            #pragma unroll
            for (int mt = 0; mt < MT; mt++) {
                ldsm_x4(af[sb][mt], aBase + baseA[mt] + (uint32_t)(((2 * s + hiA) ^ rA7[mt]) << 4));
                if (CVT_A) {
                    #pragma unroll
                    for (int v = 0; v < 4; v++)
                        af[sb][mt][v] = f2tf32(__uint_as_float(af[sb][mt][v]));
                }
            }
            #pragma unroll
            for (int p = 0; p < NP; p++)
                ldsm_x4(bf[sb][p], bBase + baseB[p] + (uint32_t)(((2 * s + hiB) ^ rB7[p]) << 4));
        };

        ldfrags(0, 0);
        #pragma unroll
        for (int s = 0; s < 4; s++) {
            if (s < 3) ldfrags((s + 1) & 1, s + 1);
            const int sb = s & 1;
            #pragma unroll
            for (int mt = 0; mt < MT; mt++)
                #pragma unroll
                for (int nt = 0; nt < NT; nt++) {
                    const int p = nt >> 1, o = (nt & 1) * 2;
                    mma_tf32(acc[mt][nt],
                             af[sb][mt][0], af[sb][mt][1], af[sb][mt][2], af[sb][mt][3],
                             bf[sb][p][o], bf[sb][p][o + 1]);
                }
        }
        __syncthreads();
    }

    #pragma unroll
    for (int mt = 0; mt < MT; mt++) {
        int r0 = brow + wm + mt * 16 + lq;
        int r1 = r0 + 8;
        #pragma unroll
        for (int nt = 0; nt < NT; nt++) {
            int c = bcol + wn + nt * 8 + lr * 2;
            if (c >= N) continue;
            float v0 = acc[mt][nt][0], v1 = acc[mt][nt][1];
            float v2 = acc[mt][nt][2], v3 = acc[mt][nt][3];
            if (bias) {
                float b0 = __ldg(bias + c), b1 = __ldg(bias + c + 1);
                v0 += b0; v1 += b1; v2 += b0; v3 += b1;
            }
            if (EPI == 1) {
                v0 = (v0 > 20.f) ? v0 : log1pf(expf(v0));
                v1 = (v1 > 20.f) ? v1 : log1pf(expf(v1));
                v2 = (v2 > 20.f) ? v2 : log1pf(expf(v2));
                v3 = (v3 > 20.f) ? v3 : log1pf(expf(v3));
            }
            if (EPI == 2) {
                const float is2 = 0.70710678118654752f;
                v0 = 0.5f * v0 * (1.f + erff(v0 * is2));
                v1 = 0.5f * v1 * (1.f + erff(v1 * is2));
                v2 = 0.5f * v2 * (1.f + erff(v2 * is2));
                v3 = 0.5f * v3 * (1.f + erff(v3 * is2));
            }
            float* p0 = C + (size_t)r0 * ldc + c;
            float* p1 = C + (size_t)r1 * ldc + c;
            if (ACC) {
                float2 o0 = *(float2*)p0, o1 = *(float2*)p1;
                v0 += o0.x; v1 += o0.y; v2 += o1.x; v3 += o1.y;
            }
            if (ROUND_OUT) {
                v0 = round_tf32(v0); v1 = round_tf32(v1);
                v2 = round_tf32(v2); v3 = round_tf32(v3);
            }
            *(float2*)p0 = make_float2(v0, v1);
            *(float2*)p1 = make_float2(v2, v3);
        }
    }
}

// ---------------- depthwise causal conv (DCONV=4) + silu ----------------
__global__ void conv_silu_kernel(const float* __restrict__ proj,
                                 const float* __restrict__ w,
                                 float* __restrict__ u)
{
    int idx = blockIdx.x * 256 + threadIdx.x;
    int d = idx & (DD - 1);
    int t = idx >> 9;
    int l = t & (LL - 1);
    const float* wd = w + d * 4;
    float acc = 0.f;
    #pragma unroll
    for (int k = 0; k < 4; k++) {
        int ll = l - 3 + k;
        if (ll >= 0) acc = fmaf(proj[(size_t)(t - 3 + k) * PW + d], wd[k], acc);
    }
    u[idx] = acc / (1.0f + expf(-acc));
}

// ---------------- chunked selective-scan, smem-staged ----------------
// grid: NCH * BB * (DD/128) = 256 blocks of 128 threads.
// bid: dg = bid & 3, b = (bid>>2) & 1, c = bid >> 3.
// Layout of P/S/h0: off = ((c*BB + b)*NSt + n)*DD + d  (d coalesced).

// Pass 1: local scan from h=0 per chunk; emit per-lane decay P and local state S.
__global__ __launch_bounds__(128) void scan_p1s(const float* __restrict__ proj,
                                                const float* __restrict__ dt,
                                                const float* __restrict__ u,
                                                float* __restrict__ P,
                                                float* __restrict__ S)
{
    const int bid = blockIdx.x;
    const int dg = bid & 3;
    const int b  = (bid >> 2) & 1;
    const int c  = bid >> 3;
    const int tid = threadIdx.x;
    const int d  = dg * 128 + tid;
    const int t0 = b * LL + c * CHL;

    __shared__ float Bs[CHL][NSt];
    for (int idx = tid; idx < CHL * NSt; idx += 128) {
        int s = idx >> 4, n = idx & 15;
        Bs[s][n] = proj[(size_t)(t0 + s) * PW + 2 * DD + RR + n];
    }
    __syncthreads();

    float h[NSt];
    #pragma unroll
    for (int n = 0; n < NSt; n++) h[n] = 0.f;
    float sdt = 0.f;

    const float* dtP = dt + (size_t)t0 * DD + d;
    const float* uP  = u  + (size_t)t0 * DD + d;
    float dtv = dtP[0], uv = uP[0];

    for (int s = 0; s < CHL; s++) {
        float dt2 = 0.f, u2 = 0.f;
        if (s + 1 < CHL) {
            dt2 = dtP[(size_t)(s + 1) * DD];
            u2  = uP [(size_t)(s + 1) * DD];
        }
        sdt += dtv;
        float e = __expf(-dtv);
        float a = 1.f;
        #pragma unroll
        for (int n = 0; n < NSt; n++) {
            a *= e;
            const float inv = -1.0f / (float)(n + 1);
            h[n] = fmaf(a, h[n], (a - 1.f) * inv * Bs[s][n] * uv);
        }
        dtv = dt2; uv = u2;
    }

    const size_t base = ((size_t)(c * BB + b) * NSt) * DD + d;
    #pragma unroll
    for (int n = 0; n < NSt; n++) {
        P[base + (size_t)n * DD] = __expf(-(float)(n + 1) * sdt);
        S[base + (size_t)n * DD] = h[n];
    }
}

// Pass 2: serial recombine over chunks -> chunk-initial states h0.
__global__ __launch_bounds__(256) void scan_p2(const float* __restrict__ P,
                                               const float* __restrict__ S,
                                               float* __restrict__ h0)
{
    int idx = blockIdx.x * 256 + threadIdx.x;     // over BB*DD*NSt = 16384
    float H = 0.f;
    #pragma unroll 4
    for (int c = 0; c < NCH; c++) {
        int off = c * (BB * DD * NSt) + idx;
        h0[off] = H;
        H = fmaf(P[off], H, S[off]);
    }
}

// Pass 3: rescan each chunk from h0, emit y.
__global__ __launch_bounds__(128) void scan_p3s(const float* __restrict__ proj,
                                                const float* __restrict__ dt,
                                                const float* __restrict__ u,
                                                const float* __restrict__ Dp,
                                                const float* __restrict__ h0,
                                                float* __restrict__ y)
{
    const int bid = blockIdx.x;
    const int dg = bid & 3;
    const int b  = (bid >> 2) & 1;
    const int c  = bid >> 3;
    const int tid = threadIdx.x;
    const int d  = dg * 128 + tid;
    const int t0 = b * LL + c * CHL;
    const float dval = Dp[d];

    __shared__ float Bs[CHL][NSt];
    __shared__ float Cs[CHL][NSt];
    for (int idx = tid; idx < CHL * NSt; idx += 128) {
        int s = idx >> 4, n = idx & 15;
        const float* row = proj + (size_t)(t0 + s) * PW + 2 * DD + RR;
        Bs[s][n] = row[n];
        Cs[s][n] = row[NSt + n];
    }
    __syncthreads();

    float h[NSt];
    const size_t base = ((size_t)(c * BB + b) * NSt) * DD + d;
    #pragma unroll
    for (int n = 0; n < NSt; n++) h[n] = h0[base + (size_t)n * DD];

    const float* dtP = dt + (size_t)t0 * DD + d;
    const float* uP  = u  + (size_t)t0 * DD + d;
    const float* zP  = proj + (size_t)t0 * PW + DD + d;
    float*       yP  = y  + (size_t)t0 * DD + d;

    float dtv = dtP[0], uv = uP[0], zv = zP[0];

    for (int s = 0; s < CHL; s++) {
        float dt2 = 0.f, u2 = 0.f, z2 = 0.f;
        if (s + 1 < CHL) {
            dt2 = dtP[(size_t)(s + 1) * DD];
            u2  = uP [(size_t)(s + 1) * DD];
            z2  = zP [(size_t)(s + 1) * PW];
        }
        float e = __expf(-dtv);
        float a = 1.f, yv = 0.f;
        #pragma unroll
        for (int n = 0; n < NSt; n++) {
            a *= e;
            const float inv = -1.0f / (float)(n + 1);
            h[n] = fmaf(a, h[n], (a - 1.f) * inv * Bs[s][n] * uv);
            yv = fmaf(Cs[s][n], h[n], yv);
        }
        float sz = zv / (1.f + __expf(-zv));
        yP[(size_t)s * DD] = round_tf32((yv + uv * dval) * sz);
        dtv = dt2; uv = u2; zv = z2;
    }
}

// ---------------- host-side GEMM dispatch ----------------
template <int BM, int BN, int EPI, bool ACC, bool CVT_A, bool RO>
static inline void launch_gemm(const float* A, int lda, const float* W, int ldw,
                               const float* bias, float* C, int ldc,
                               int M, int N, int K)
{
    dim3 grid(M / BM, (N + BN - 1) / BN);
    size_t smem = (size_t)(2 * BM * 32 + 2 * BN * 32) * 4;
    gemm_tc4<BM, BN, EPI, ACC, CVT_A, RO><<<grid, 128, smem>>>(A, lda, W, ldw, bias, C, ldc, M, N, K);
}

// ---------------- entry point ----------------
extern "C" void kernel_launch(void* const* d_in, const int* in_sizes, int n_in,
                              void* d_out, int out_size)
{
    const int*   x_t     = (const int*)  d_in[0];
    const int*   t_in    = (const int*)  d_in[1];
    const float* tok_emb = (const float*)d_in[2];
    const float* tmlp_w1 = (const float*)d_in[3];
    const float* tmlp_b1 = (const float*)d_in[4];
    const float* tmlp_w2 = (const float*)d_in[5];
    const float* tmlp_b2 = (const float*)d_in[6];
    const float* ln1_g   = (const float*)d_in[7];
    const float* ln1_b   = (const float*)d_in[8];
    const float* in_w    = (const float*)d_in[9];
    const float* conv_w  = (const float*)d_in[10];
    const float* dt_w    = (const float*)d_in[11];
    const float* dt_b    = (const float*)d_in[12];
    const float* D_p     = (const float*)d_in[13];
    const float* out_w   = (const float*)d_in[14];
    const float* ln2_g   = (const float*)d_in[15];
    const float* ln2_b   = (const float*)d_in[16];
    const float* mlp_w1  = (const float*)d_in[17];
    const float* mlp_b1  = (const float*)d_in[18];
    const float* mlp_w2  = (const float*)d_in[19];
    const float* mlp_b2  = (const float*)d_in[20];
    const float* lno_g   = (const float*)d_in[21];
    const float* lno_b   = (const float*)d_in[22];
    const float* head_w  = (const float*)d_in[23];
    const float* head_b  = (const float*)d_in[24];
    float* out = (float*)d_out;

    float *x, *ln, *proj, *u, *dtb, *y, *ff, *te, *wtf, *sP, *sS, *sH0;
    cudaGetSymbolAddress((void**)&x,    g_x);
    cudaGetSymbolAddress((void**)&ln,   g_ln);
    cudaGetSymbolAddress((void**)&proj, g_proj);
    cudaGetSymbolAddress((void**)&u,    g_u);
    cudaGetSymbolAddress((void**)&dtb,  g_dt);
    cudaGetSymbolAddress((void**)&y,    g_y);
    cudaGetSymbolAddress((void**)&ff,   g_ff);
    cudaGetSymbolAddress((void**)&te,   g_te);
    cudaGetSymbolAddress((void**)&wtf,  g_wtf);
    cudaGetSymbolAddress((void**)&sP,   g_scanP);
    cudaGetSymbolAddress((void**)&sS,   g_scanS);
    cudaGetSymbolAddress((void**)&sH0,  g_scanH0);

    // raise dynamic smem limits (host API)
    cudaFuncSetAttribute((const void*)gemm_tc4<64, 64, 0, false, false, false>,  cudaFuncAttributeMaxDynamicSharedMemorySize, (2*64*32+2*64*32)*4);
    cudaFuncSetAttribute((const void*)gemm_tc4<64, 32, 1, false, true, false>,   cudaFuncAttributeMaxDynamicSharedMemorySize, (2*64*32+2*32*32)*4);
    cudaFuncSetAttribute((const void*)gemm_tc4<64, 32, 0, true, false, false>,   cudaFuncAttributeMaxDynamicSharedMemorySize, (2*64*32+2*32*32)*4);
    cudaFuncSetAttribute((const void*)gemm_tc4<64, 128, 2, false, false, true>,  cudaFuncAttributeMaxDynamicSharedMemorySize, (2*64*32+2*128*32)*4);
    cudaFuncSetAttribute((const void*)gemm_tc4<64, 128, 0, false, false, false>, cudaFuncAttributeMaxDynamicSharedMemorySize, (2*64*32+2*128*32)*4);

    float* inw_t  = wtf + OFF_INW;
    float* dtw_t  = wtf + OFF_DTW;
    float* outw_t = wtf + OFF_OUTW;
    float* w1_t   = wtf + OFF_W1;
    float* w2_t   = wtf + OFF_W2;
    float* head_t = wtf + OFF_HEAD;

    // pre-round all GEMM weights to the tf32 grid (once per call)
    {
        int n;
        n = DEPTH * PW * DD / 4;   roundw_kernel<<<(n + 255) / 256, 256>>>((const float4*)in_w,   (float4*)inw_t,  n);
        n = DEPTH * DD * RR / 4;   roundw_kernel<<<(n + 255) / 256, 256>>>((const float4*)dt_w,   (float4*)dtw_t,  n);
        n = DEPTH * DD * DD / 4;   roundw_kernel<<<(n + 255) / 256, 256>>>((const float4*)out_w,  (float4*)outw_t, n);
        n = DEPTH * DFF * DD / 4;  roundw_kernel<<<(n + 255) / 256, 256>>>((const float4*)mlp_w1, (float4*)w1_t,   n);
        n = DEPTH * DD * DFF / 4;  roundw_kernel<<<(n + 255) / 256, 256>>>((const float4*)mlp_w2, (float4*)w2_t,   n);
        n = VOC * DD / 4;          roundw_kernel<<<(n + 255) / 256, 256>>>((const float4*)head_w, (float4*)head_t, n);
    }

    te_kernel<<<BB, 256>>>(t_in, tmlp_w1, tmlp_b1, tmlp_w2, tmlp_b2, te);
    embed_kernel<<<TT * DD / 256, 256>>>(x_t, tok_emb, te, x);

    const int scan_blocks = NCH * BB * (DD / 128);   // 256

    for (int i = 0; i < DEPTH; i++) {
        ln_kernel<<<TT, 256>>>(x, ln1_g + i * DD, ln1_b + i * DD, ln);
        launch_gemm<64, 64, 0, false, false, false>(ln, DD, inw_t + (size_t)i * PW * DD, DD, nullptr,
                                                    proj, PW, TT, PW, DD);
        conv_silu_kernel<<<TT * DD / 256, 256>>>(proj, conv_w + (size_t)i * DD * 4, u);
        launch_gemm<64, 32, 1, false, true, false>(proj + 2 * DD, PW, dtw_t + (size_t)i * DD * RR, RR, dt_b + i * DD,
                                                   dtb, DD, TT, DD, RR);
        scan_p1s<<<scan_blocks, 128>>>(proj, dtb, u, sP, sS);
        scan_p2<<<BB * DD * NSt / 256, 256>>>(sP, sS, sH0);
        scan_p3s<<<scan_blocks, 128>>>(proj, dtb, u, D_p + i * DD, sH0, y);
        launch_gemm<64, 32, 0, true, false, false>(y, DD, outw_t + (size_t)i * DD * DD, DD, nullptr,
                                                   x, DD, TT, DD, DD);
        ln_kernel<<<TT, 256>>>(x, ln2_g + i * DD, ln2_b + i * DD, ln);
        launch_gemm<64, 128, 2, false, false, true>(ln, DD, w1_t + (size_t)i * DFF * DD, DD, mlp_b1 + i * DFF,
                                                    ff, DFF, TT, DFF, DD);
        launch_gemm<64, 32, 0, true, false, false>(ff, DFF, w2_t + (size_t)i * DD * DFF, DFF, mlp_b2 + i * DD,
                                                   x, DD, TT, DD, DFF);
    }

    ln_kernel<<<TT, 256>>>(x, lno_g, lno_b, ln);
    launch_gemm<64, 128, 0, false, false, false>(ln, DD, head_t, DD, head_b, out, VOC, TT, VOC, DD);
}

// round 8
// speedup vs baseline: 4.3381x; 1.4098x over previous
#include <cuda_runtime.h>
#include <cuda_fp16.h>
#include <math.h>
#include <stdint.h>

// ---------------- problem constants ----------------
#define TT    2048        // B*L tokens
#define BB    2
#define LL    1024
#define DD    512
#define NSt   16
#define RR    32
#define PW    1088        // 2D + R + 2N
#define DFF   2048
#define VOC   50000
#define DEPTH 6
#define NCH   32          // scan chunks
#define CHL   32          // chunk length

// ---------------- device scratch (no allocs allowed) ----------------
__device__ float  g_x   [TT * DD];
__device__ __half g_lnh [TT * DD];
__device__ float  g_proj[TT * PW];
__device__ float  g_u   [TT * DD];
__device__ float  g_dt  [TT * DD];
__device__ __half g_yh  [TT * DD];
__device__ __half g_ffh [TT * DFF];
__device__ float  g_te  [BB * DD];
__device__ float  g_scanP [NCH * BB * DD * NSt];
__device__ float  g_scanS [NCH * BB * DD * NSt];
__device__ float  g_scanH0[NCH * BB * DD * NSt];

// fp16 weights
#define OFF_INW  0
#define OFF_OUTW 3342336              // + 6*1088*512
#define OFF_W1   4915200              // + 6*512*512
#define OFF_W2   11206656             // + 6*2048*512
#define OFF_HEAD 17498112             // + 6*512*2048
#define WH_TOTAL 43098112             // + 50000*512
__device__ __half g_wh[WH_TOTAL];
__device__ float  g_dtw[DEPTH * DD * RR];   // tf32-rounded dt weights

// ---------------- PTX helpers ----------------
__device__ __forceinline__ void cp_async16(void* dst, const void* src, bool pred) {
    uint32_t d = (uint32_t)__cvta_generic_to_shared(dst);
    int sz = pred ? 16 : 0;
    asm volatile("cp.async.cg.shared.global [%0], [%1], 16, %2;\n" :: "r"(d), "l"(src), "r"(sz));
}
__device__ __forceinline__ void cp_commit() { asm volatile("cp.async.commit_group;\n"); }
template <int NN>
__device__ __forceinline__ void cp_wait() { asm volatile("cp.async.wait_group %0;\n" :: "n"(NN)); }

__device__ __forceinline__ uint32_t f2tf32(float x) {
    uint32_t r;
    asm("cvt.rna.tf32.f32 %0, %1;\n" : "=r"(r) : "f"(x));
    return r;
}
__device__ __forceinline__ float round_tf32(float x) { return __uint_as_float(f2tf32(x)); }

__device__ __forceinline__ void mma_tf32(float c[4],
                                         uint32_t a0, uint32_t a1, uint32_t a2, uint32_t a3,
                                         uint32_t b0, uint32_t b1) {
    asm volatile(
        "mma.sync.aligned.m16n8k8.row.col.f32.tf32.tf32.f32 "
        "{%0,%1,%2,%3}, {%4,%5,%6,%7}, {%8,%9}, {%0,%1,%2,%3};\n"
        : "+f"(c[0]), "+f"(c[1]), "+f"(c[2]), "+f"(c[3])
        : "r"(a0), "r"(a1), "r"(a2), "r"(a3), "r"(b0), "r"(b1));
}
__device__ __forceinline__ void mma_f16(float c[4],
                                        uint32_t a0, uint32_t a1, uint32_t a2, uint32_t a3,
                                        uint32_t b0, uint32_t b1) {
    asm volatile(
        "mma.sync.aligned.m16n8k16.row.col.f32.f16.f16.f32 "
        "{%0,%1,%2,%3}, {%4,%5,%6,%7}, {%8,%9}, {%0,%1,%2,%3};\n"
        : "+f"(c[0]), "+f"(c[1]), "+f"(c[2]), "+f"(c[3])
        : "r"(a0), "r"(a1), "r"(a2), "r"(a3), "r"(b0), "r"(b1));
}

__device__ __forceinline__ void ldsm_x4(uint32_t r[4], uint32_t saddr) {
    asm volatile("ldmatrix.sync.aligned.m8n8.x4.shared.b16 {%0,%1,%2,%3}, [%4];\n"
        : "=r"(r[0]), "=r"(r[1]), "=r"(r[2]), "=r"(r[3]) : "r"(saddr));
}

// ---------------- weight conversion kernels ----------------
__global__ void cvtw_kernel(const float4* __restrict__ s, __half2* __restrict__ d, int n4) {
    int i = blockIdx.x * 256 + threadIdx.x;
    if (i < n4) {
        float4 v = s[i];
        d[2 * i]     = __floats2half2_rn(v.x, v.y);
        d[2 * i + 1] = __floats2half2_rn(v.z, v.w);
    }
}
__global__ void roundw_kernel(const float4* __restrict__ s, float4* __restrict__ d, int n4) {
    int i = blockIdx.x * 256 + threadIdx.x;
    if (i < n4) {
        float4 v = s[i];
        v.x = round_tf32(v.x); v.y = round_tf32(v.y);
        v.z = round_tf32(v.z); v.w = round_tf32(v.w);
        d[i] = v;
    }
}

// ---------------- time-embedding MLP (tiny) ----------------
__global__ void te_kernel(const int* __restrict__ t_in,
                          const float* __restrict__ w1, const float* __restrict__ b1,
                          const float* __restrict__ w2, const float* __restrict__ b2,
                          float* __restrict__ te)
{
    int b = blockIdx.x;
    int tid = threadIdx.x;            // 256 threads
    __shared__ float s0[DD];
    __shared__ float h1[4 * DD];

    double tv = (double)t_in[b];
    {
        double f = exp((double)tid * (-9.210340371976184 / 255.0));
        double e = tv * f;
        s0[tid]       = (float)sin(e);
        s0[tid + 256] = (float)cos(e);
    }
    __syncthreads();

    for (int j = tid; j < 4 * DD; j += 256) {
        const float* wr = w1 + (size_t)j * DD;
        float acc = b1[j];
        #pragma unroll 8
        for (int k = 0; k < DD; k++) acc = fmaf(s0[k], wr[k], acc);
        h1[j] = acc / (1.0f + expf(-acc));
    }
    __syncthreads();

    for (int j = tid; j < DD; j += 256) {
        const float* wr = w2 + (size_t)j * (4 * DD);
        float acc = b2[j];
        #pragma unroll 8
        for (int k = 0; k < 4 * DD; k++) acc = fmaf(h1[k], wr[k], acc);
        te[b * DD + j] = acc;
    }
}

// ---------------- embedding gather + te add ----------------
__global__ void embed_kernel(const int* __restrict__ x_t,
                             const float* __restrict__ tok_emb,
                             const float* __restrict__ te,
                             float* __restrict__ x)
{
    int idx = blockIdx.x * 256 + threadIdx.x;
    int d = idx & (DD - 1);
    int t = idx >> 9;
    int b = t >> 10;
    int tok = x_t[t];
    x[idx] = tok_emb[(size_t)tok * DD + d] + te[b * DD + d];
}

// ---------------- LayerNorm (two-pass); fp16 output ----------------
__global__ __launch_bounds__(256) void ln_kernel(const float* __restrict__ x,
                                                 const float* __restrict__ g,
                                                 const float* __restrict__ bta,
                                                 __half* __restrict__ o)
{
    int t = blockIdx.x;
    int tid = threadIdx.x;
    const float* row = x + (size_t)t * DD;
    float v0 = row[tid], v1 = row[tid + 256];

    __shared__ float red[8];
    __shared__ float mean_s, rstd_s;

    float s = v0 + v1;
    #pragma unroll
    for (int off = 16; off > 0; off >>= 1) s += __shfl_xor_sync(0xffffffffu, s, off);
    if ((tid & 31) == 0) red[tid >> 5] = s;
    __syncthreads();
    if (tid == 0) {
        float tot = 0.f;
        #pragma unroll
        for (int i = 0; i < 8; i++) tot += red[i];
        mean_s = tot * (1.0f / DD);
    }
    __syncthreads();
    float mu = mean_s;
    float d0 = v0 - mu, d1 = v1 - mu;
    float q = d0 * d0 + d1 * d1;
    #pragma unroll
    for (int off = 16; off > 0; off >>= 1) q += __shfl_xor_sync(0xffffffffu, q, off);
    if ((tid & 31) == 0) red[tid >> 5] = q;
    __syncthreads();
    if (tid == 0) {
        float tot = 0.f;
        #pragma unroll
        for (int i = 0; i < 8; i++) tot += red[i];
        rstd_s = rsqrtf(tot * (1.0f / DD) + 1e-5f);
    }
    __syncthreads();
    float rs = rstd_s;
    o[(size_t)t * DD + tid]       = __float2half_rn(d0 * rs * g[tid]       + bta[tid]);
    o[(size_t)t * DD + tid + 256] = __float2half_rn(d1 * rs * g[tid + 256] + bta[tid + 256]);
}

// ---------------- FP16 tensor-core GEMM: C[M,N] = A[M,K] @ W[N,K]^T ----------------
// BM=64, BN in {32,64,128}, k-tile = 64 halves (4 x k16 mma steps), 128 threads
// (2x2 warps, warp tile 32 x BN/2), cp.async double-buffered SW128-equivalent
// chunk-XOR smem, ldmatrix fragments, fp32 accumulate.
// EPI: 0 none, 2 exact gelu. ACC: C(+)= (fp32 C only). HALF_OUT: store __half.
template <int BN, int EPI, bool ACC, bool HALF_OUT>
__global__ __launch_bounds__(128) void gemm_h(
    const __half* __restrict__ A, int lda,
    const __half* __restrict__ W, int ldw,
    const float* __restrict__ bias,
    void* __restrict__ Cv, int ldc,
    int M, int N, int K)
{
    constexpr int MT = 2;              // m16 tiles per warp
    constexpr int NT = BN / 16;        // n8 tiles per warp
    constexpr int NP = NT / 2;         // ldmatrix.x4 B loads per s-step
    constexpr int AHALF = 64 * 64;     // halfs per A k-tile buffer
    constexpr int BHALF = BN * 64;

    extern __shared__ __half smh[];
    const uint32_t sbase = (uint32_t)__cvta_generic_to_shared(smh);

    const int tid  = threadIdx.x;
    const int lane = tid & 31;
    const int wid  = tid >> 5;
    const int wm   = (wid & 1) * 32;
    const int wn   = (wid >> 1) * (BN / 2);
    const int brow = blockIdx.x * 64;
    const int bcol = blockIdx.y * BN;
    const int lq   = lane >> 2;
    const int lr   = lane & 3;

    // ldmatrix addressing (byte offsets within a k-tile buffer; rows are 128B)
    const int hiA = lane >> 4;             // k16-half selector for A
    const int hiB = (lane >> 3) & 1;       // k16-half selector for B
    uint32_t rowA[MT]; int rA7[MT];
    #pragma unroll
    for (int mt = 0; mt < MT; mt++) {
        int r = wm + mt * 16 + (lane & 15);
        rowA[mt] = (uint32_t)r * 128;
        rA7[mt] = r & 7;
    }
    uint32_t rowB[NP]; int rB7[NP];
    #pragma unroll
    for (int p = 0; p < NP; p++) {
        int r = wn + p * 16 + (lane & 7) + ((lane >> 4) << 3);
        rowB[p] = (uint32_t)r * 128;
        rB7[p] = r & 7;
    }

    float acc[MT][NT][4];
    #pragma unroll
    for (int i = 0; i < MT; i++)
        #pragma unroll
        for (int j = 0; j < NT; j++)
            #pragma unroll
            for (int v = 0; v < 4; v++) acc[i][j][v] = 0.f;

    const int KT = K >> 6;   // k-tiles of 64 halves

    auto load_tile = [&](int buf, int k0) {
        // A: 64 rows x 8 chunks(16B); 2 threads/row, 4 chunks each
        {
            int r = tid >> 1, cb = (tid & 1) * 4;
            const __half* src = A + (size_t)(brow + r) * lda + k0 + cb * 8;
            __half* drow = smh + buf * AHALF + r * 64;
            #pragma unroll
            for (int c = 0; c < 4; c++)
                cp_async16(drow + (((cb + c) ^ (r & 7)) << 3), src + c * 8, true);
        }
        __half* bb = smh + 2 * AHALF + buf * BHALF;
        if (BN == 128) {
            int r = tid;
            const __half* src = W + (size_t)(bcol + r) * ldw + k0;
            bool pv = (bcol + r) < N;
            __half* drow = bb + r * 64;
            #pragma unroll
            for (int c = 0; c < 8; c++)
                cp_async16(drow + ((c ^ (r & 7)) << 3), src + c * 8, pv);
        } else if (BN == 64) {
            int r = tid >> 1, cb = (tid & 1) * 4;
            const __half* src = W + (size_t)(bcol + r) * ldw + k0 + cb * 8;
            bool pv = (bcol + r) < N;
            __half* drow = bb + r * 64;
            #pragma unroll
            for (int c = 0; c < 4; c++)
                cp_async16(drow + (((cb + c) ^ (r & 7)) << 3), src + c * 8, pv);
        } else {  // BN == 32
            int r = tid >> 2, cb = (tid & 3) * 2;
            const __half* src = W + (size_t)(bcol + r) * ldw + k0 + cb * 8;
            bool pv = (bcol + r) < N;
            __half* drow = bb + r * 64;
            #pragma unroll
            for (int c = 0; c < 2; c++)
                cp_async16(drow + (((cb + c) ^ (r & 7)) << 3), src + c * 8, pv);
        }
    };

    load_tile(0, 0);
    cp_commit();

    uint32_t af[2][MT][4], bf[2][NP][4];

    for (int kt = 0; kt < KT; kt++) {
        if (kt + 1 < KT) {
            load_tile((kt + 1) & 1, (kt + 1) * 64);
            cp_commit();
            cp_wait<1>();
        } else {
            cp_wait<0>();
        }
        __syncthreads();

        const uint32_t aB = sbase + (uint32_t)((kt & 1) * AHALF) * 2;
        const uint32_t bB = sbase + (uint32_t)(2 * AHALF + (kt & 1) * BHALF) * 2;

        auto ldfrags = [&](int sb, int s) {
            #pragma unroll
            for (int mt = 0; mt < MT; mt++)
                ldsm_x4(af[sb][mt], aB + rowA[mt] + (uint32_t)(((2 * s + hiA) ^ rA7[mt]) << 4));
            #pragma unroll
            for (int p = 0; p < NP; p++)
                ldsm_x4(bf[sb][p], bB + rowB[p] + (uint32_t)(((2 * s + hiB) ^ rB7[p]) << 4));
        };

        ldfrags(0, 0);
        #pragma unroll
        for (int s = 0; s < 4; s++) {       // 4 x k16 steps
            if (s < 3) ldfrags((s + 1) & 1, s + 1);
            const int sb = s & 1;
            #pragma unroll
            for (int mt = 0; mt < MT; mt++)
                #pragma unroll
                for (int nt = 0; nt < NT; nt++) {
                    const int p = nt >> 1, o = (nt & 1) * 2;
                    mma_f16(acc[mt][nt],
                            af[sb][mt][0], af[sb][mt][1], af[sb][mt][2], af[sb][mt][3],
                            bf[sb][p][o], bf[sb][p][o + 1]);
                }
        }
        __syncthreads();
    }

    // ---- epilogue ----
    #pragma unroll
    for (int mt = 0; mt < MT; mt++) {
        int r0 = brow + wm + mt * 16 + lq;
        int r1 = r0 + 8;
        #pragma unroll
        for (int nt = 0; nt < NT; nt++) {
            int c = bcol + wn + nt * 8 + lr * 2;
            if (c >= N) continue;
            float v0 = acc[mt][nt][0], v1 = acc[mt][nt][1];
            float v2 = acc[mt][nt][2], v3 = acc[mt][nt][3];
            if (bias) {
                float b0 = __ldg(bias + c), b1 = __ldg(bias + c + 1);
                v0 += b0; v1 += b1; v2 += b0; v3 += b1;
            }
            if (EPI == 2) {
                const float is2 = 0.70710678118654752f;
                v0 = 0.5f * v0 * (1.f + erff(v0 * is2));
                v1 = 0.5f * v1 * (1.f + erff(v1 * is2));
                v2 = 0.5f * v2 * (1.f + erff(v2 * is2));
                v3 = 0.5f * v3 * (1.f + erff(v3 * is2));
            }
            if (HALF_OUT) {
                __half* cp0 = (__half*)Cv + (size_t)r0 * ldc + c;
                __half* cp1 = (__half*)Cv + (size_t)r1 * ldc + c;
                *(__half2*)cp0 = __floats2half2_rn(v0, v1);
                *(__half2*)cp1 = __floats2half2_rn(v2, v3);
            } else {
                float* p0 = (float*)Cv + (size_t)r0 * ldc + c;
                float* p1 = (float*)Cv + (size_t)r1 * ldc + c;
                if (ACC) {
                    float2 o0 = *(float2*)p0, o1 = *(float2*)p1;
                    v0 += o0.x; v1 += o0.y; v2 += o1.x; v3 += o1.y;
                }
                *(float2*)p0 = make_float2(v0, v1);
                *(float2*)p1 = make_float2(v2, v3);
            }
        }
    }
}

// ---------------- TF32 GEMM (dt projection only: K=32, softplus, CVT_A) ----------------
__global__ __launch_bounds__(128) void gemm_dt(
    const float* __restrict__ A, int lda,
    const float* __restrict__ W, int ldw,
    const float* __restrict__ bias,
    float* __restrict__ C, int ldc,
    int M, int N, int K)
{
    constexpr int BM = 64, BN = 32;
    constexpr int MT = 2, NT = 2, NP = 1;
    constexpr int ABUF = BM * 32, BBUF = BN * 32;

    extern __shared__ float smf[];
    const uint32_t smem_u = (uint32_t)__cvta_generic_to_shared(smf);

    const int tid  = threadIdx.x;
    const int lane = tid & 31;
    const int wid  = tid >> 5;
    const int wm   = (wid & 1) * 32;
    const int wn   = (wid >> 1) * 16;
    const int brow = blockIdx.x * BM;
    const int bcol = blockIdx.y * BN;
    const int lq   = lane >> 2;
    const int lr   = lane & 3;

    const int hiA = lane >> 4;
    const int hiB = (lane >> 3) & 1;
    uint32_t baseA[MT]; int rA7[MT];
    #pragma unroll
    for (int mt = 0; mt < MT; mt++) {
        int r = wm + mt * 16 + (lane & 15);
        baseA[mt] = (uint32_t)r * 128;
        rA7[mt] = r & 7;
    }
    uint32_t baseB; int rB7;
    {
        int r = wn + (lane & 7) + ((lane >> 4) << 3);
        baseB = (uint32_t)r * 128;
        rB7 = r & 7;
    }

    float acc[MT][NT][4];
    #pragma unroll
    for (int i = 0; i < MT; i++)
        #pragma unroll
        for (int j = 0; j < NT; j++)
            #pragma unroll
            for (int v = 0; v < 4; v++) acc[i][j][v] = 0.f;

    // single k-tile (K=32)
    {
        int m = tid >> 1, cb = (tid & 1) * 4;
        const float* src = A + (size_t)(brow + m) * lda + cb * 4;
        float* drow = smf + m * 32;
        #pragma unroll
        for (int c = 0; c < 4; c++)
            cp_async16(drow + (((cb + c) ^ (m & 7)) << 2), src + c * 4, true);
    }
    {
        int n = tid >> 2, cb = (tid & 3) * 2;
        const float* src = W + (size_t)(bcol + n) * ldw + cb * 4;
        bool pv = (bcol + n) < N;
        float* drow = smf + ABUF + n * 32;
        #pragma unroll
        for (int c = 0; c < 2; c++)
            cp_async16(drow + (((cb + c) ^ (n & 7)) << 2), src + c * 4, pv);
    }
    cp_commit();
    cp_wait<0>();
    __syncthreads();

    #pragma unroll
    for (int s = 0; s < 4; s++) {
        uint32_t af[MT][4], bfr[4];
        #pragma unroll
        for (int mt = 0; mt < MT; mt++) {
            ldsm_x4(af[mt], smem_u + baseA[mt] + (uint32_t)(((2 * s + hiA) ^ rA7[mt]) << 4));
            #pragma unroll
            for (int v = 0; v < 4; v++)
                af[mt][v] = f2tf32(__uint_as_float(af[mt][v]));
        }
        ldsm_x4(bfr, smem_u + (uint32_t)ABUF * 4 + baseB + (uint32_t)(((2 * s + hiB) ^ rB7) << 4));
        #pragma unroll
        for (int mt = 0; mt < MT; mt++)
            #pragma unroll
            for (int nt = 0; nt < NT; nt++)
                mma_tf32(acc[mt][nt], af[mt][0], af[mt][1], af[mt][2], af[mt][3],
                         bfr[nt * 2], bfr[nt * 2 + 1]);
    }

    #pragma unroll
    for (int mt = 0; mt < MT; mt++) {
        int r0 = brow + wm + mt * 16 + lq;
        int r1 = r0 + 8;
        #pragma unroll
        for (int nt = 0; nt < NT; nt++) {
            int c = bcol + wn + nt * 8 + lr * 2;
            float v0 = acc[mt][nt][0], v1 = acc[mt][nt][1];
            float v2 = acc[mt][nt][2], v3 = acc[mt][nt][3];
            float b0 = __ldg(bias + c), b1 = __ldg(bias + c + 1);
            v0 += b0; v1 += b1; v2 += b0; v3 += b1;
            v0 = (v0 > 20.f) ? v0 : log1pf(expf(v0));
            v1 = (v1 > 20.f) ? v1 : log1pf(expf(v1));
            v2 = (v2 > 20.f) ? v2 : log1pf(expf(v2));
            v3 = (v3 > 20.f) ? v3 : log1pf(expf(v3));
            *(float2*)(C + (size_t)r0 * ldc + c) = make_float2(v0, v1);
            *(float2*)(C + (size_t)r1 * ldc + c) = make_float2(v2, v3);
        }
    }
}

// ---------------- depthwise causal conv (DCONV=4) + silu ----------------
__global__ void conv_silu_kernel(const float* __restrict__ proj,
                                 const float* __restrict__ w,
                                 float* __restrict__ u)
{
    int idx = blockIdx.x * 256 + threadIdx.x;
    int d = idx & (DD - 1);
    int t = idx >> 9;
    int l = t & (LL - 1);
    const float* wd = w + d * 4;
    float acc = 0.f;
    #pragma unroll
    for (int k = 0; k < 4; k++) {
        int ll = l - 3 + k;
        if (ll >= 0) acc = fmaf(proj[(size_t)(t - 3 + k) * PW + d], wd[k], acc);
    }
    u[idx] = acc / (1.0f + expf(-acc));
}

// ---------------- chunked selective-scan, smem-staged ----------------
__global__ __launch_bounds__(128) void scan_p1s(const float* __restrict__ proj,
                                                const float* __restrict__ dt,
                                                const float* __restrict__ u,
                                                float* __restrict__ P,
                                                float* __restrict__ S)
{
    const int bid = blockIdx.x;
    const int dg = bid & 3;
    const int b  = (bid >> 2) & 1;
    const int c  = bid >> 3;
    const int tid = threadIdx.x;
    const int d  = dg * 128 + tid;
    const int t0 = b * LL + c * CHL;

    __shared__ float Bs[CHL][NSt];
    for (int idx = tid; idx < CHL * NSt; idx += 128) {
        int s = idx >> 4, n = idx & 15;
        Bs[s][n] = proj[(size_t)(t0 + s) * PW + 2 * DD + RR + n];
    }
    __syncthreads();

    float h[NSt];
    #pragma unroll
    for (int n = 0; n < NSt; n++) h[n] = 0.f;
    float sdt = 0.f;

    const float* dtP = dt + (size_t)t0 * DD + d;
    const float* uP  = u  + (size_t)t0 * DD + d;
    float dtv = dtP[0], uv = uP[0];

    for (int s = 0; s < CHL; s++) {
        float dt2 = 0.f, u2 = 0.f;
        if (s + 1 < CHL) {
            dt2 = dtP[(size_t)(s + 1) * DD];
            u2  = uP [(size_t)(s + 1) * DD];
        }
        sdt += dtv;
        float e = __expf(-dtv);
        float a = 1.f;
        #pragma unroll
        for (int n = 0; n < NSt; n++) {
            a *= e;
            const float inv = -1.0f / (float)(n + 1);
            h[n] = fmaf(a, h[n], (a - 1.f) * inv * Bs[s][n] * uv);
        }
        dtv = dt2; uv = u2;
    }

    const size_t base = ((size_t)(c * BB + b) * NSt) * DD + d;
    #pragma unroll
    for (int n = 0; n < NSt; n++) {
        P[base + (size_t)n * DD] = __expf(-(float)(n + 1) * sdt);
        S[base + (size_t)n * DD] = h[n];
    }
}

__global__ __launch_bounds__(256) void scan_p2(const float* __restrict__ P,
                                               const float* __restrict__ S,
                                               float* __restrict__ h0)
{
    int idx = blockIdx.x * 256 + threadIdx.x;     // over BB*DD*NSt = 16384
    float H = 0.f;
    #pragma unroll 4
    for (int c = 0; c < NCH; c++) {
        int off = c * (BB * DD * NSt) + idx;
        h0[off] = H;
        H = fmaf(P[off], H, S[off]);
    }
}

__global__ __launch_bounds__(128) void scan_p3s(const float* __restrict__ proj,
                                                const float* __restrict__ dt,
                                                const float* __restrict__ u,
                                                const float* __restrict__ Dp,
                                                const float* __restrict__ h0,
                                                __half* __restrict__ y)
{
    const int bid = blockIdx.x;
    const int dg = bid & 3;
    const int b  = (bid >> 2) & 1;
    const int c  = bid >> 3;
    const int tid = threadIdx.x;
    const int d  = dg * 128 + tid;
    const int t0 = b * LL + c * CHL;
    const float dval = Dp[d];

    __shared__ float Bs[CHL][NSt];
    __shared__ float Cs[CHL][NSt];
    for (int idx = tid; idx < CHL * NSt; idx += 128) {
        int s = idx >> 4, n = idx & 15;
        const float* row = proj + (size_t)(t0 + s) * PW + 2 * DD + RR;
        Bs[s][n] = row[n];
        Cs[s][n] = row[NSt + n];
    }
    __syncthreads();

    float h[NSt];
    const size_t base = ((size_t)(c * BB + b) * NSt) * DD + d;
    #pragma unroll
    for (int n = 0; n < NSt; n++) h[n] = h0[base + (size_t)n * DD];

    const float* dtP = dt + (size_t)t0 * DD + d;
    const float* uP  = u  + (size_t)t0 * DD + d;
    const float* zP  = proj + (size_t)t0 * PW + DD + d;
    __half*      yP  = y  + (size_t)t0 * DD + d;

    float dtv = dtP[0], uv = uP[0], zv = zP[0];

    for (int s = 0; s < CHL; s++) {
        float dt2 = 0.f, u2 = 0.f, z2 = 0.f;
        if (s + 1 < CHL) {
            dt2 = dtP[(size_t)(s + 1) * DD];
            u2  = uP [(size_t)(s + 1) * DD];
            z2  = zP [(size_t)(s + 1) * PW];
        }
        float e = __expf(-dtv);
        float a = 1.f, yv = 0.f;
        #pragma unroll
        for (int n = 0; n < NSt; n++) {
            a *= e;
            const float inv = -1.0f / (float)(n + 1);
            h[n] = fmaf(a, h[n], (a - 1.f) * inv * Bs[s][n] * uv);
            yv = fmaf(Cs[s][n], h[n], yv);
        }
        float sz = zv / (1.f + __expf(-zv));
        yP[(size_t)s * DD] = __float2half_rn((yv + uv * dval) * sz);
        dtv = dt2; uv = u2; zv = z2;
    }
}

// ---------------- host-side GEMM dispatch ----------------
template <int BN, int EPI, bool ACC, bool HALF_OUT>
static inline void launch_h(const __half* A, int lda, const __half* W, int ldw,
                            const float* bias, void* C, int ldc,
                            int M, int N, int K)
{
    dim3 grid(M / 64, (N + BN - 1) / BN);
    size_t smem = (size_t)(2 * 64 * 64 + 2 * BN * 64) * sizeof(__half);
    gemm_h<BN, EPI, ACC, HALF_OUT><<<grid, 128, smem>>>(A, lda, W, ldw, bias, C, ldc, M, N, K);
}

// ---------------- entry point ----------------
extern "C" void kernel_launch(void* const* d_in, const int* in_sizes, int n_in,
                              void* d_out, int out_size)
{
    const int*   x_t     = (const int*)  d_in[0];
    const int*   t_in    = (const int*)  d_in[1];
    const float* tok_emb = (const float*)d_in[2];
    const float* tmlp_w1 = (const float*)d_in[3];
    const float* tmlp_b1 = (const float*)d_in[4];
    const float* tmlp_w2 = (const float*)d_in[5];
    const float* tmlp_b2 = (const float*)d_in[6];
    const float* ln1_g   = (const float*)d_in[7];
    const float* ln1_b   = (const float*)d_in[8];
    const float* in_w    = (const float*)d_in[9];
    const float* conv_w  = (const float*)d_in[10];
    const float* dt_w    = (const float*)d_in[11];
    const float* dt_b    = (const float*)d_in[12];
    const float* D_p     = (const float*)d_in[13];
    const float* out_w   = (const float*)d_in[14];
    const float* ln2_g   = (const float*)d_in[15];
    const float* ln2_b   = (const float*)d_in[16];
    const float* mlp_w1  = (const float*)d_in[17];
    const float* mlp_b1  = (const float*)d_in[18];
    const float* mlp_w2  = (const float*)d_in[19];
    const float* mlp_b2  = (const float*)d_in[20];
    const float* lno_g   = (const float*)d_in[21];
    const float* lno_b   = (const float*)d_in[22];
    const float* head_w  = (const float*)d_in[23];
    const float* head_b  = (const float*)d_in[24];
    float* out = (float*)d_out;

    float *x, *proj, *u, *dtb, *te, *sP, *sS, *sH0, *dtw;
    __half *lnh, *yh, *ffh, *wh;
    cudaGetSymbolAddress((void**)&x,    g_x);
    cudaGetSymbolAddress((void**)&lnh,  g_lnh);
    cudaGetSymbolAddress((void**)&proj, g_proj);
    cudaGetSymbolAddress((void**)&u,    g_u);
    cudaGetSymbolAddress((void**)&dtb,  g_dt);
    cudaGetSymbolAddress((void**)&yh,   g_yh);
    cudaGetSymbolAddress((void**)&ffh,  g_ffh);
    cudaGetSymbolAddress((void**)&te,   g_te);
    cudaGetSymbolAddress((void**)&wh,   g_wh);
    cudaGetSymbolAddress((void**)&dtw,  g_dtw);
    cudaGetSymbolAddress((void**)&sP,   g_scanP);
    cudaGetSymbolAddress((void**)&sS,   g_scanS);
    cudaGetSymbolAddress((void**)&sH0,  g_scanH0);

    // dynamic smem limits
    cudaFuncSetAttribute((const void*)gemm_h<64, 0, false, false>,  cudaFuncAttributeMaxDynamicSharedMemorySize, (2*64*64 + 2*64*64) * 2);
    cudaFuncSetAttribute((const void*)gemm_h<32, 0, true, false>,   cudaFuncAttributeMaxDynamicSharedMemorySize, (2*64*64 + 2*32*64) * 2);
    cudaFuncSetAttribute((const void*)gemm_h<128, 2, false, true>,  cudaFuncAttributeMaxDynamicSharedMemorySize, (2*64*64 + 2*128*64) * 2);
    cudaFuncSetAttribute((const void*)gemm_dt, cudaFuncAttributeMaxDynamicSharedMemorySize, (64*32 + 32*32) * 4);

    __half* wh_inw  = wh + OFF_INW;
    __half* wh_outw = wh + OFF_OUTW;
    __half* wh_w1   = wh + OFF_W1;
    __half* wh_w2   = wh + OFF_W2;
    __half* wh_head = wh + OFF_HEAD;

    const int scan_blocks = NCH * BB * (DD / 128);   // 256
    const size_t dt_smem = (64 * 32 + 32 * 32) * 4;

    // launch order chosen so launch #6 = first in-proj GEMM (ncu -s 5 -c 1)
    te_kernel<<<BB, 256>>>(t_in, tmlp_w1, tmlp_b1, tmlp_w2, tmlp_b2, te);          // 1
    embed_kernel<<<TT * DD / 256, 256>>>(x_t, tok_emb, te, x);                      // 2
    {
        int n = DEPTH * DD * RR / 4;
        roundw_kernel<<<(n + 255) / 256, 256>>>((const float4*)dt_w, (float4*)dtw, n);   // 3
    }
    {
        int n = DEPTH * PW * DD / 4;
        cvtw_kernel<<<(n + 255) / 256, 256>>>((const float4*)in_w, (__half2*)wh_inw, n); // 4
    }
    ln_kernel<<<TT, 256>>>(x, ln1_g, ln1_b, lnh);                                   // 5
    launch_h<64, 0, false, false>(lnh, DD, wh_inw, DD, nullptr, proj, PW, TT, PW, DD);  // 6 <- profiled
    {
        int n;
        n = DEPTH * DD * DD / 4;   cvtw_kernel<<<(n + 255) / 256, 256>>>((const float4*)out_w,  (__half2*)wh_outw, n);
        n = DEPTH * DFF * DD / 4;  cvtw_kernel<<<(n + 255) / 256, 256>>>((const float4*)mlp_w1, (__half2*)wh_w1,   n);
        n = DEPTH * DD * DFF / 4;  cvtw_kernel<<<(n + 255) / 256, 256>>>((const float4*)mlp_w2, (__half2*)wh_w2,   n);
        n = VOC * DD / 4;          cvtw_kernel<<<(n + 255) / 256, 256>>>((const float4*)head_w, (__half2*)wh_head, n);
    }

    for (int i = 0; i < DEPTH; i++) {
        if (i > 0) {
            ln_kernel<<<TT, 256>>>(x, ln1_g + i * DD, ln1_b + i * DD, lnh);
            launch_h<64, 0, false, false>(lnh, DD, wh_inw + (size_t)i * PW * DD, DD, nullptr,
                                          proj, PW, TT, PW, DD);
        }
        conv_silu_kernel<<<TT * DD / 256, 256>>>(proj, conv_w + (size_t)i * DD * 4, u);
        {
            dim3 grid(TT / 64, DD / 32);
            gemm_dt<<<grid, 128, dt_smem>>>(proj + 2 * DD, PW, dtw + (size_t)i * DD * RR, RR,
                                            dt_b + i * DD, dtb, DD, TT, DD, RR);
        }
        scan_p1s<<<scan_blocks, 128>>>(proj, dtb, u, sP, sS);
        scan_p2<<<BB * DD * NSt / 256, 256>>>(sP, sS, sH0);
        scan_p3s<<<scan_blocks, 128>>>(proj, dtb, u, D_p + i * DD, sH0, yh);
        launch_h<32, 0, true, false>(yh, DD, wh_outw + (size_t)i * DD * DD, DD, nullptr,
                                     x, DD, TT, DD, DD);
        ln_kernel<<<TT, 256>>>(x, ln2_g + i * DD, ln2_b + i * DD, lnh);
        launch_h<128, 2, false, true>(lnh, DD, wh_w1 + (size_t)i * DFF * DD, DD, mlp_b1 + i * DFF,
                                      ffh, DFF, TT, DFF, DD);
        launch_h<32, 0, true, false>(ffh, DFF, wh_w2 + (size_t)i * DD * DFF, DFF, mlp_b2 + i * DD,
                                     x, DD, TT, DD, DFF);
    }

    ln_kernel<<<TT, 256>>>(x, lno_g, lno_b, lnh);
    launch_h<64, 0, false, false>(lnh, DD, wh_head, DD, head_b, out, VOC, TT, VOC, DD);
}